// round 2
// baseline (speedup 1.0000x reference)
#include <cuda_runtime.h>
#include <math.h>

#define D_IN 1024
#define D_H  512
#define NBINS 10

// ---------------- scratch (no allocations allowed) ----------------
__device__ unsigned int g_min_enc[4];
__device__ unsigned int g_max_enc[4];
__device__ int          g_hist[4][NBINS];
__device__ float        g_wglobal[2];
__device__ __align__(16) float g_W0b[D_H * D_IN];   // blended W0
__device__ __align__(16) float g_W1b[D_H];          // blended W1
__device__ __align__(16) float g_partial[4 * 65536];

// monotonic float<->uint encoding for atomic min/max
__device__ __forceinline__ unsigned int enc_f(float f) {
    unsigned int u = __float_as_uint(f);
    return (u & 0x80000000u) ? ~u : (u | 0x80000000u);
}
__device__ __forceinline__ float dec_f(unsigned int u) {
    u = (u & 0x80000000u) ? (u ^ 0x80000000u) : ~u;
    return __uint_as_float(u);
}

__global__ void init_kernel() {
    int t = threadIdx.x;
    if (t < 4) { g_min_enc[t] = 0xFFFFFFFFu; g_max_enc[t] = 0u; }
    if (t < 4 * NBINS) g_hist[t / NBINS][t % NBINS] = 0;
}

__global__ void minmax_kernel(const float* __restrict__ p, int n, int slot) {
    unsigned int mn = 0xFFFFFFFFu, mx = 0u;
    for (int i = blockIdx.x * blockDim.x + threadIdx.x; i < n;
         i += gridDim.x * blockDim.x) {
        unsigned int e = enc_f(p[i]);
        mn = min(mn, e); mx = max(mx, e);
    }
#pragma unroll
    for (int o = 16; o; o >>= 1) {
        mn = min(mn, __shfl_down_sync(0xffffffffu, mn, o));
        mx = max(mx, __shfl_down_sync(0xffffffffu, mx, o));
    }
    __shared__ unsigned int smn[8], smx[8];
    int w = threadIdx.x >> 5, l = threadIdx.x & 31;
    if (l == 0) { smn[w] = mn; smx[w] = mx; }
    __syncthreads();
    if (threadIdx.x == 0) {
        int nw = blockDim.x >> 5;
        for (int i = 1; i < nw; i++) { mn = min(mn, smn[i]); mx = max(mx, smx[i]); }
        atomicMin(&g_min_enc[slot], mn);
        atomicMax(&g_max_enc[slot], mx);
    }
}

// Histogram replicating jnp half-open bins EXACTLY: lower = lo + i*scale,
// upper = lo + (i+1)*scale, no fma contraction (C_CONST=500 makes the entropy
// difference sensitive to bin-count errors).
__global__ void hist_kernel(const float* __restrict__ p, int n, int slot) {
    __shared__ int sh[NBINS];
    if (threadIdx.x < NBINS) sh[threadIdx.x] = 0;
    __syncthreads();
    float lo = dec_f(g_min_enc[slot]);
    float hi = dec_f(g_max_enc[slot]);
    float scale = __fdiv_rn(__fsub_rn(hi, lo), 10.0f);
    for (int i = blockIdx.x * blockDim.x + threadIdx.x; i < n;
         i += gridDim.x * blockDim.x) {
        float v = p[i];
#pragma unroll
        for (int b = 0; b < NBINS; b++) {
            float lower = __fadd_rn(lo, __fmul_rn((float)b, scale));
            float upper = __fadd_rn(lo, __fmul_rn((float)(b + 1), scale));
            if (v >= lower && v < upper) { atomicAdd(&sh[b], 1); break; }
        }
    }
    __syncthreads();
    if (threadIdx.x < NBINS) atomicAdd(&g_hist[slot][threadIdx.x], sh[threadIdx.x]);
}

__global__ void scalar_kernel() {
    if (threadIdx.x != 0) return;
    float H[4];
    const int ns[4] = {D_H * D_IN, D_H * D_IN, D_H, D_H};
    for (int a = 0; a < 4; a++) {
        float h = 0.f;
        for (int b = 0; b < NBINS; b++) {
            float pp = (float)g_hist[a][b] / (float)ns[a];
            if (pp > 0.f) h += -pp * logf(pp);
        }
        H[a] = h;
    }
    const float API = 0.12732395447351627f;  // 0.4/pi
    g_wglobal[0] = API * atanf(500.0f * (H[0] - H[1])) + 0.5f;
    g_wglobal[1] = API * atanf(500.0f * (H[2] - H[3])) + 0.5f;
}

__device__ __forceinline__ float blend_one(float base, float graft, float d, float wg) {
    float wl = 1.0f / (1.0f + expf(-d));
    float wb = wg * (1.0f - expf(-wg * wl));
    float og = 1.0f - wg;
    float wgf = og * (1.0f - expf(-og * (1.0f - wl)));
    // softmax over {wb,wgf} == sigmoid(wb - wgf) on the base slot
    float s = 1.0f / (1.0f + expf(wgf - wb));
    return base * s + graft * (1.0f - s);
}

// d0 = |w0-g0| @ p0^T, fused blend epilogue -> g_W0b.  M=512, N=1024, K=1024.
#define W0_BM 64
#define W0_BN 64
#define W0_BK 16
__global__ __launch_bounds__(256) void w0_blend_kernel(
    const float* __restrict__ w0, const float* __restrict__ g0,
    const float* __restrict__ p0) {
    __shared__ __align__(16) float As[W0_BK][W0_BM];
    __shared__ __align__(16) float Bs[W0_BK][W0_BN];
    int tid = threadIdx.x;
    int rowBase = blockIdx.y * W0_BM;  // over D_H
    int colBase = blockIdx.x * W0_BN;  // over D_IN
    int lr = tid >> 2;
    int lv = (tid & 3) * 4;
    int tr = tid >> 4, tc = tid & 15;
    float acc[4][4] = {};
    for (int kt = 0; kt < D_IN; kt += W0_BK) {
        float4 aw = *(const float4*)(w0 + (rowBase + lr) * D_IN + kt + lv);
        float4 ag = *(const float4*)(g0 + (rowBase + lr) * D_IN + kt + lv);
        float4 bb = *(const float4*)(p0 + (colBase + lr) * D_IN + kt + lv);
        __syncthreads();
        As[lv + 0][lr] = fabsf(aw.x - ag.x);
        As[lv + 1][lr] = fabsf(aw.y - ag.y);
        As[lv + 2][lr] = fabsf(aw.z - ag.z);
        As[lv + 3][lr] = fabsf(aw.w - ag.w);
        Bs[lv + 0][lr] = bb.x; Bs[lv + 1][lr] = bb.y;
        Bs[lv + 2][lr] = bb.z; Bs[lv + 3][lr] = bb.w;
        __syncthreads();
#pragma unroll
        for (int k = 0; k < W0_BK; k++) {
            float4 a = *(const float4*)&As[k][tr * 4];
            float4 b = *(const float4*)&Bs[k][tc * 4];
            float av[4] = {a.x, a.y, a.z, a.w};
            float bv[4] = {b.x, b.y, b.z, b.w};
#pragma unroll
            for (int i = 0; i < 4; i++)
#pragma unroll
                for (int j = 0; j < 4; j++) acc[i][j] += av[i] * bv[j];
        }
    }
    float wg = g_wglobal[0];
#pragma unroll
    for (int i = 0; i < 4; i++) {
        int o = rowBase + tr * 4 + i;
#pragma unroll
        for (int j = 0; j < 4; j++) {
            int c = colBase + tc * 4 + j;
            g_W0b[o * D_IN + c] =
                blend_one(w0[o * D_IN + c], g0[o * D_IN + c], acc[i][j], wg);
        }
    }
}

__global__ void w1_blend_kernel(const float* __restrict__ w1,
                                const float* __restrict__ g1,
                                const float* __restrict__ p1) {
    int i = blockIdx.x * blockDim.x + threadIdx.x;
    if (i >= D_H) return;
    float d = 0.f;
    for (int k = 0; k < D_H; k++) d += fabsf(w1[k] - g1[k]) * p1[i * D_H + k];
    g_W1b[i] = blend_one(w1[i], g1[i], d, g_wglobal[1]);
}

// Main fused GEMM: h = relu(x @ W0b^T + b0); partial[cb][row] = sum_j W1b[j]*h
#define BM 128
#define BN 128
#define BK 8
__global__ __launch_bounds__(256) void gemm_fused_kernel(
    const float* __restrict__ x, const float* __restrict__ b0, int Brows) {
    __shared__ __align__(16) float As[BK][BM];
    __shared__ __align__(16) float Bs[BK][BN];
    __shared__ float red[BM][16];
    int tid = threadIdx.x;
    int rowBase = blockIdx.x * BM;
    int colBase = blockIdx.y * BN;
    int lr = tid >> 1;          // 0..127
    int lv = (tid & 1) * 4;     // 0 or 4
    int tr = tid >> 4, tc = tid & 15;
    const float* xA = x + (rowBase + lr) * D_IN + lv;
    const float* wB = g_W0b + (colBase + lr) * D_IN + lv;
    float acc[8][8] = {};
    for (int kt = 0; kt < D_IN; kt += BK) {
        float4 a4 = *(const float4*)(xA + kt);
        float4 b4 = *(const float4*)(wB + kt);
        __syncthreads();
        As[lv + 0][lr] = a4.x; As[lv + 1][lr] = a4.y;
        As[lv + 2][lr] = a4.z; As[lv + 3][lr] = a4.w;
        Bs[lv + 0][lr] = b4.x; Bs[lv + 1][lr] = b4.y;
        Bs[lv + 2][lr] = b4.z; Bs[lv + 3][lr] = b4.w;
        __syncthreads();
#pragma unroll
        for (int k = 0; k < BK; k++) {
            float4 a0 = *(const float4*)&As[k][tr * 8];
            float4 a1 = *(const float4*)&As[k][tr * 8 + 4];
            float4 c0 = *(const float4*)&Bs[k][tc * 8];
            float4 c1 = *(const float4*)&Bs[k][tc * 8 + 4];
            float av[8] = {a0.x, a0.y, a0.z, a0.w, a1.x, a1.y, a1.z, a1.w};
            float bv[8] = {c0.x, c0.y, c0.z, c0.w, c1.x, c1.y, c1.z, c1.w};
#pragma unroll
            for (int i = 0; i < 8; i++)
#pragma unroll
                for (int j = 0; j < 8; j++) acc[i][j] += av[i] * bv[j];
        }
    }
    // epilogue: relu + weighted reduction over hidden columns
    float b0v[8], w1v[8];
#pragma unroll
    for (int j = 0; j < 8; j++) {
        int c = colBase + tc * 8 + j;
        b0v[j] = b0[c];
        w1v[j] = g_W1b[c];
    }
    float rowsum[8];
#pragma unroll
    for (int i = 0; i < 8; i++) {
        float s = 0.f;
#pragma unroll
        for (int j = 0; j < 8; j++) {
            float h = acc[i][j] + b0v[j];
            s += fmaxf(h, 0.f) * w1v[j];
        }
        rowsum[i] = s;
    }
    __syncthreads();
#pragma unroll
    for (int i = 0; i < 8; i++) red[tr * 8 + i][tc] = rowsum[i];
    __syncthreads();
    if (tid < BM) {
        float s = 0.f;
#pragma unroll
        for (int c = 0; c < 16; c++) s += red[tid][c];
        g_partial[blockIdx.y * Brows + rowBase + tid] = s;
    }
}

__global__ void reduce_kernel(float* __restrict__ out, const float* __restrict__ b1,
                              int Brows) {
    int b = blockIdx.x * blockDim.x + threadIdx.x;
    if (b < Brows)
        out[b] = b1[0] + g_partial[b] + g_partial[Brows + b] +
                 g_partial[2 * Brows + b] + g_partial[3 * Brows + b];
}

extern "C" void kernel_launch(void* const* d_in, const int* in_sizes, int n_in,
                              void* d_out, int out_size) {
    const float* x  = (const float*)d_in[0];
    const float* w0 = (const float*)d_in[1];
    const float* b0 = (const float*)d_in[2];
    const float* w1 = (const float*)d_in[3];
    const float* b1 = (const float*)d_in[4];
    const float* p0 = (const float*)d_in[5];
    const float* p1 = (const float*)d_in[6];
    const float* g0 = (const float*)d_in[7];
    const float* g1 = (const float*)d_in[8];
    float* out = (float*)d_out;
    int Brows = in_sizes[0] / D_IN;
    const int nbig = D_H * D_IN;

    init_kernel<<<1, 64>>>();
    minmax_kernel<<<128, 256>>>(w0, nbig, 0);
    minmax_kernel<<<128, 256>>>(g0, nbig, 1);
    minmax_kernel<<<1, 256>>>(w1, D_H, 2);
    minmax_kernel<<<1, 256>>>(g1, D_H, 3);
    hist_kernel<<<128, 256>>>(w0, nbig, 0);
    hist_kernel<<<128, 256>>>(g0, nbig, 1);
    hist_kernel<<<1, 256>>>(w1, D_H, 2);
    hist_kernel<<<1, 256>>>(g1, D_H, 3);
    scalar_kernel<<<1, 32>>>();
    w0_blend_kernel<<<dim3(D_IN / W0_BN, D_H / W0_BM), 256>>>(w0, g0, p0);
    w1_blend_kernel<<<2, 256>>>(w1, g1, p1);
    gemm_fused_kernel<<<dim3(Brows / BM, D_H / BN), 256>>>(x, b0, Brows);
    reduce_kernel<<<(Brows + 255) / 256, 256>>>(out, b1, Brows);
}

// round 4
// speedup vs baseline: 1.9229x; 1.9229x over previous
#include <cuda_runtime.h>
#include <cuda_bf16.h>
#include <math.h>
#include <stdint.h>

#define D_IN 1024
#define D_H  512
#define NBINS 10
#define MAXB 65536

// ---------------- scratch (no allocations allowed) ----------------
__device__ unsigned int g_min_enc[4];
__device__ unsigned int g_max_enc[4];
__device__ int          g_hist[4][NBINS];
__device__ float        g_wglobal[2];
__device__ __align__(16) __nv_bfloat16 g_W0hi[D_H * D_IN];
__device__ __align__(16) __nv_bfloat16 g_W0lo[D_H * D_IN];
__device__ __align__(16) float g_W1b[D_H];
__device__ __align__(16) float g_partial[4 * MAXB];
__device__ __align__(16) __nv_bfloat16 g_Xhi[(size_t)MAXB * D_IN];
__device__ __align__(16) __nv_bfloat16 g_Xlo[(size_t)MAXB * D_IN];

// ---------------- PTX helpers ----------------
__device__ __forceinline__ uint32_t smem_u32(const void* p) {
    uint32_t a;
    asm("{ .reg .u64 t; cvta.to.shared.u64 t, %1; cvt.u32.u64 %0, t; }"
        : "=r"(a) : "l"(p));
    return a;
}
__device__ __forceinline__ void cp16(uint32_t dst, const void* src) {
    asm volatile("cp.async.cg.shared.global [%0], [%1], 16;"
                 :: "r"(dst), "l"(src) : "memory");
}
__device__ __forceinline__ void cp_commit() {
    asm volatile("cp.async.commit_group;" ::: "memory");
}
template <int N>
__device__ __forceinline__ void cp_wait() {
    asm volatile("cp.async.wait_group %0;" :: "n"(N) : "memory");
}
__device__ __forceinline__ void ldsm4(uint32_t* r, uint32_t addr) {
    asm volatile("ldmatrix.sync.aligned.m8n8.x4.shared.b16 {%0,%1,%2,%3}, [%4];"
                 : "=r"(r[0]), "=r"(r[1]), "=r"(r[2]), "=r"(r[3]) : "r"(addr));
}
__device__ __forceinline__ void ldsm2(uint32_t* r, uint32_t addr) {
    asm volatile("ldmatrix.sync.aligned.m8n8.x2.shared.b16 {%0,%1}, [%2];"
                 : "=r"(r[0]), "=r"(r[1]) : "r"(addr));
}
__device__ __forceinline__ void mma_bf16(float* c, const uint32_t* a,
                                         const uint32_t* b) {
    asm volatile(
        "mma.sync.aligned.m16n8k16.row.col.f32.bf16.bf16.f32 "
        "{%0,%1,%2,%3}, {%4,%5,%6,%7}, {%8,%9}, {%0,%1,%2,%3};"
        : "+f"(c[0]), "+f"(c[1]), "+f"(c[2]), "+f"(c[3])
        : "r"(a[0]), "r"(a[1]), "r"(a[2]), "r"(a[3]), "r"(b[0]), "r"(b[1]));
}

// ---------------- entropy path (exact jnp half-open bins) ----------
__device__ __forceinline__ unsigned int enc_f(float f) {
    unsigned int u = __float_as_uint(f);
    return (u & 0x80000000u) ? ~u : (u | 0x80000000u);
}
__device__ __forceinline__ float dec_f(unsigned int u) {
    u = (u & 0x80000000u) ? (u ^ 0x80000000u) : ~u;
    return __uint_as_float(u);
}

__global__ void init_kernel() {
    int t = threadIdx.x;
    if (t < 4) { g_min_enc[t] = 0xFFFFFFFFu; g_max_enc[t] = 0u; }
    if (t < 4 * NBINS) g_hist[t / NBINS][t % NBINS] = 0;
}

__global__ void minmax_kernel(const float* __restrict__ p, int n, int slot) {
    unsigned int mn = 0xFFFFFFFFu, mx = 0u;
    for (int i = blockIdx.x * blockDim.x + threadIdx.x; i < n;
         i += gridDim.x * blockDim.x) {
        unsigned int e = enc_f(p[i]);
        mn = min(mn, e); mx = max(mx, e);
    }
#pragma unroll
    for (int o = 16; o; o >>= 1) {
        mn = min(mn, __shfl_down_sync(0xffffffffu, mn, o));
        mx = max(mx, __shfl_down_sync(0xffffffffu, mx, o));
    }
    __shared__ unsigned int smn[8], smx[8];
    int w = threadIdx.x >> 5, l = threadIdx.x & 31;
    if (l == 0) { smn[w] = mn; smx[w] = mx; }
    __syncthreads();
    if (threadIdx.x == 0) {
        int nw = blockDim.x >> 5;
        for (int i = 1; i < nw; i++) { mn = min(mn, smn[i]); mx = max(mx, smx[i]); }
        atomicMin(&g_min_enc[slot], mn);
        atomicMax(&g_max_enc[slot], mx);
    }
}

__global__ void hist_kernel(const float* __restrict__ p, int n, int slot) {
    __shared__ int sh[NBINS];
    if (threadIdx.x < NBINS) sh[threadIdx.x] = 0;
    __syncthreads();
    float lo = dec_f(g_min_enc[slot]);
    float hi = dec_f(g_max_enc[slot]);
    float scale = __fdiv_rn(__fsub_rn(hi, lo), 10.0f);
    for (int i = blockIdx.x * blockDim.x + threadIdx.x; i < n;
         i += gridDim.x * blockDim.x) {
        float v = p[i];
#pragma unroll
        for (int b = 0; b < NBINS; b++) {
            float lower = __fadd_rn(lo, __fmul_rn((float)b, scale));
            float upper = __fadd_rn(lo, __fmul_rn((float)(b + 1), scale));
            if (v >= lower && v < upper) { atomicAdd(&sh[b], 1); break; }
        }
    }
    __syncthreads();
    if (threadIdx.x < NBINS) atomicAdd(&g_hist[slot][threadIdx.x], sh[threadIdx.x]);
}

__global__ void scalar_kernel() {
    if (threadIdx.x != 0) return;
    float H[4];
    const int ns[4] = {D_H * D_IN, D_H * D_IN, D_H, D_H};
    for (int a = 0; a < 4; a++) {
        float h = 0.f;
        for (int b = 0; b < NBINS; b++) {
            float pp = (float)g_hist[a][b] / (float)ns[a];
            if (pp > 0.f) h += -pp * logf(pp);
        }
        H[a] = h;
    }
    const float API = 0.12732395447351627f;  // 0.4/pi
    g_wglobal[0] = API * atanf(500.0f * (H[0] - H[1])) + 0.5f;
    g_wglobal[1] = API * atanf(500.0f * (H[2] - H[3])) + 0.5f;
}

__device__ __forceinline__ float blend_one(float base, float graft, float d, float wg) {
    float wl = 1.0f / (1.0f + expf(-d));
    float wb = wg * (1.0f - expf(-wg * wl));
    float og = 1.0f - wg;
    float wgf = og * (1.0f - expf(-og * (1.0f - wl)));
    float s = 1.0f / (1.0f + expf(wgf - wb));  // softmax pair == sigmoid(diff)
    return base * s + graft * (1.0f - s);
}

// d0 = |w0-g0| @ p0^T, fused blend epilogue -> split bf16 hi/lo
#define W0_BM 64
#define W0_BN 64
#define W0_BK 16
__global__ __launch_bounds__(256) void w0_blend_kernel(
    const float* __restrict__ w0, const float* __restrict__ g0,
    const float* __restrict__ p0) {
    __shared__ __align__(16) float As[W0_BK][W0_BM];
    __shared__ __align__(16) float Bs[W0_BK][W0_BN];
    int tid = threadIdx.x;
    int rowBase = blockIdx.y * W0_BM;  // over D_H
    int colBase = blockIdx.x * W0_BN;  // over D_IN
    int lr = tid >> 2;
    int lv = (tid & 3) * 4;
    int tr = tid >> 4, tc = tid & 15;
    float acc[4][4] = {};
    for (int kt = 0; kt < D_IN; kt += W0_BK) {
        float4 aw = *(const float4*)(w0 + (rowBase + lr) * D_IN + kt + lv);
        float4 ag = *(const float4*)(g0 + (rowBase + lr) * D_IN + kt + lv);
        float4 bb = *(const float4*)(p0 + (colBase + lr) * D_IN + kt + lv);
        __syncthreads();
        As[lv + 0][lr] = fabsf(aw.x - ag.x);
        As[lv + 1][lr] = fabsf(aw.y - ag.y);
        As[lv + 2][lr] = fabsf(aw.z - ag.z);
        As[lv + 3][lr] = fabsf(aw.w - ag.w);
        Bs[lv + 0][lr] = bb.x; Bs[lv + 1][lr] = bb.y;
        Bs[lv + 2][lr] = bb.z; Bs[lv + 3][lr] = bb.w;
        __syncthreads();
#pragma unroll
        for (int k = 0; k < W0_BK; k++) {
            float4 a = *(const float4*)&As[k][tr * 4];
            float4 b = *(const float4*)&Bs[k][tc * 4];
            float av[4] = {a.x, a.y, a.z, a.w};
            float bv[4] = {b.x, b.y, b.z, b.w};
#pragma unroll
            for (int i = 0; i < 4; i++)
#pragma unroll
                for (int j = 0; j < 4; j++) acc[i][j] += av[i] * bv[j];
        }
    }
    float wg = g_wglobal[0];
#pragma unroll
    for (int i = 0; i < 4; i++) {
        int o = rowBase + tr * 4 + i;
#pragma unroll
        for (int j = 0; j < 4; j++) {
            int c = colBase + tc * 4 + j;
            float v = blend_one(w0[o * D_IN + c], g0[o * D_IN + c], acc[i][j], wg);
            __nv_bfloat16 h = __float2bfloat16(v);
            __nv_bfloat16 l = __float2bfloat16(v - __bfloat162float(h));
            g_W0hi[o * D_IN + c] = h;
            g_W0lo[o * D_IN + c] = l;
        }
    }
}

__global__ void w1_blend_kernel(const float* __restrict__ w1,
                                const float* __restrict__ g1,
                                const float* __restrict__ p1) {
    int i = blockIdx.x * blockDim.x + threadIdx.x;
    if (i >= D_H) return;
    float d = 0.f;
    for (int k = 0; k < D_H; k++) d += fabsf(w1[k] - g1[k]) * p1[i * D_H + k];
    g_W1b[i] = blend_one(w1[i], g1[i], d, g_wglobal[1]);
}

// Split x fp32 -> bf16 hi + bf16 residual lo.
__global__ void split_x_kernel(const float4* __restrict__ x, int n4) {
    int i = blockIdx.x * blockDim.x + threadIdx.x;
    if (i >= n4) return;
    float4 v = x[i];
    float vv[4] = {v.x, v.y, v.z, v.w};
    unsigned short hh[4], ll[4];
#pragma unroll
    for (int j = 0; j < 4; j++) {
        __nv_bfloat16 h = __float2bfloat16(vv[j]);
        __nv_bfloat16 l = __float2bfloat16(vv[j] - __bfloat162float(h));
        hh[j] = __bfloat16_as_ushort(h);
        ll[j] = __bfloat16_as_ushort(l);
    }
    uint2 ph = make_uint2((uint32_t)hh[0] | ((uint32_t)hh[1] << 16),
                          (uint32_t)hh[2] | ((uint32_t)hh[3] << 16));
    uint2 pl = make_uint2((uint32_t)ll[0] | ((uint32_t)ll[1] << 16),
                          (uint32_t)ll[2] | ((uint32_t)ll[3] << 16));
    ((uint2*)g_Xhi)[i] = ph;
    ((uint2*)g_Xlo)[i] = pl;
}

// ---------------- main GEMM: mma.sync bf16 x3 fp32-emulation -----------------
// CTA tile 128x128, BK=32, 3 operand passes (hi*hi, hi*lo, lo*hi) accumulated
// in fp32. Epilogue fuses relu(h+b0) dot W1 -> per-(rowblock,colblock) partial.
#define GBM 128
#define GBN 128
#define NITER 96   // (D_IN/32) * 3 passes

__global__ __launch_bounds__(256) void gemm_mma_kernel(
    const float* __restrict__ b0, int Brows) {
    __shared__ __align__(16) __nv_bfloat16 sA[2][GBM * 40];
    __shared__ __align__(16) __nv_bfloat16 sB[2][GBN * 40];
    __shared__ float red[GBM][4];

    const int tid = threadIdx.x;
    const int wid = tid >> 5, lane = tid & 31;
    const int wm = wid >> 2;      // 0..1  (64-row warp tile)
    const int wn = wid & 3;       // 0..3  (32-col warp tile)
    const int rowBase = blockIdx.x * GBM;
    const int nBase = blockIdx.y * GBN;

    const __nv_bfloat16* Apass[3] = {g_Xhi, g_Xhi, g_Xlo};
    const __nv_bfloat16* Bpass[3] = {g_W0hi, g_W0lo, g_W0hi};

    uint32_t sAu[2] = {smem_u32(&sA[0][0]), smem_u32(&sA[1][0])};
    uint32_t sBu[2] = {smem_u32(&sB[0][0]), smem_u32(&sB[1][0])};

    float acc[4][4][4] = {};

    auto load_tile = [&](int it, int buf) {
        int p = it >> 5, kt = it & 31;
        const __nv_bfloat16* As = Apass[p] + (size_t)rowBase * D_IN + kt * 32;
        const __nv_bfloat16* Bs = Bpass[p] + (size_t)nBase * D_IN + kt * 32;
#pragma unroll
        for (int h = 0; h < 2; h++) {
            int q = tid + h * 256;           // 0..511 granules of 16B
            int r = q >> 2, g = q & 3;
            uint32_t doff = (uint32_t)(r * 80 + g * 16);
            cp16(sAu[buf] + doff, As + (size_t)r * D_IN + g * 8);
            cp16(sBu[buf] + doff, Bs + (size_t)r * D_IN + g * 8);
        }
        cp_commit();
    };

    load_tile(0, 0);
    for (int it = 0; it < NITER; ++it) {
        int buf = it & 1;
        if (it + 1 < NITER) {
            load_tile(it + 1, buf ^ 1);
            cp_wait<1>();
        } else {
            cp_wait<0>();
        }
        __syncthreads();
#pragma unroll
        for (int ks = 0; ks < 2; ks++) {
            uint32_t a[4][4], b[4][2];
#pragma unroll
            for (int mi = 0; mi < 4; mi++) {
                uint32_t addr = sAu[buf] +
                    (uint32_t)((wm * 64 + mi * 16 + (lane & 15)) * 80 +
                               ks * 32 + (lane >> 4) * 16);
                ldsm4(a[mi], addr);
            }
#pragma unroll
            for (int ni = 0; ni < 4; ni++) {
                uint32_t addr = sBu[buf] +
                    (uint32_t)((wn * 32 + ni * 8 + (lane & 7)) * 80 +
                               ks * 32 + ((lane >> 3) & 1) * 16);
                ldsm2(b[ni], addr);
            }
#pragma unroll
            for (int mi = 0; mi < 4; mi++)
#pragma unroll
                for (int ni = 0; ni < 4; ni++)
                    mma_bf16(acc[mi][ni], a[mi], b[ni]);
        }
        __syncthreads();
    }

    // ---- epilogue: relu(acc + b0) dot W1 over this CTA's 128 hidden cols ----
    float w1v[4][2], b0v[4][2];
#pragma unroll
    for (int ni = 0; ni < 4; ni++) {
        int c = nBase + wn * 32 + ni * 8 + 2 * (lane & 3);
        w1v[ni][0] = g_W1b[c];     w1v[ni][1] = g_W1b[c + 1];
        b0v[ni][0] = __ldg(b0 + c); b0v[ni][1] = __ldg(b0 + c + 1);
    }
#pragma unroll
    for (int mi = 0; mi < 4; mi++) {
        float r0 = 0.f, r1 = 0.f;
#pragma unroll
        for (int ni = 0; ni < 4; ni++) {
            r0 += fmaxf(acc[mi][ni][0] + b0v[ni][0], 0.f) * w1v[ni][0];
            r0 += fmaxf(acc[mi][ni][1] + b0v[ni][1], 0.f) * w1v[ni][1];
            r1 += fmaxf(acc[mi][ni][2] + b0v[ni][0], 0.f) * w1v[ni][0];
            r1 += fmaxf(acc[mi][ni][3] + b0v[ni][1], 0.f) * w1v[ni][1];
        }
        r0 += __shfl_xor_sync(0xffffffffu, r0, 1);
        r0 += __shfl_xor_sync(0xffffffffu, r0, 2);
        r1 += __shfl_xor_sync(0xffffffffu, r1, 1);
        r1 += __shfl_xor_sync(0xffffffffu, r1, 2);
        if ((lane & 3) == 0) {
            int rr = wm * 64 + mi * 16 + (lane >> 2);
            red[rr][wn] = r0;
            red[rr + 8][wn] = r1;
        }
    }
    __syncthreads();
    if (tid < GBM) {
        float s = red[tid][0] + red[tid][1] + red[tid][2] + red[tid][3];
        g_partial[(size_t)blockIdx.y * Brows + rowBase + tid] = s;
    }
}

__global__ void reduce_kernel(float* __restrict__ out, const float* __restrict__ b1,
                              int Brows) {
    int b = blockIdx.x * blockDim.x + threadIdx.x;
    if (b < Brows)
        out[b] = b1[0] + g_partial[b] + g_partial[Brows + b] +
                 g_partial[2 * (size_t)Brows + b] + g_partial[3 * (size_t)Brows + b];
}

extern "C" void kernel_launch(void* const* d_in, const int* in_sizes, int n_in,
                              void* d_out, int out_size) {
    const float* x  = (const float*)d_in[0];
    const float* w0 = (const float*)d_in[1];
    const float* b0 = (const float*)d_in[2];
    const float* w1 = (const float*)d_in[3];
    const float* b1 = (const float*)d_in[4];
    const float* p0 = (const float*)d_in[5];
    const float* p1 = (const float*)d_in[6];
    const float* g0 = (const float*)d_in[7];
    const float* g1 = (const float*)d_in[8];
    float* out = (float*)d_out;
    int Brows = in_sizes[0] / D_IN;
    const int nbig = D_H * D_IN;
    int n4 = Brows * D_IN / 4;

    init_kernel<<<1, 64>>>();
    minmax_kernel<<<128, 256>>>(w0, nbig, 0);
    minmax_kernel<<<128, 256>>>(g0, nbig, 1);
    minmax_kernel<<<1, 256>>>(w1, D_H, 2);
    minmax_kernel<<<1, 256>>>(g1, D_H, 3);
    hist_kernel<<<128, 256>>>(w0, nbig, 0);
    hist_kernel<<<128, 256>>>(g0, nbig, 1);
    hist_kernel<<<1, 256>>>(w1, D_H, 2);
    hist_kernel<<<1, 256>>>(g1, D_H, 3);
    scalar_kernel<<<1, 32>>>();
    w0_blend_kernel<<<dim3(D_IN / W0_BN, D_H / W0_BM), 256>>>(w0, g0, p0);
    w1_blend_kernel<<<2, 256>>>(w1, g1, p1);
    split_x_kernel<<<(n4 + 255) / 256, 256>>>((const float4*)x, n4);
    gemm_mma_kernel<<<dim3(Brows / GBM, D_H / GBN), 256>>>(b0, Brows);
    reduce_kernel<<<(Brows + 255) / 256, 256>>>(out, b1, Brows);
}

// round 6
// speedup vs baseline: 2.3025x; 1.1974x over previous
#include <cuda_runtime.h>
#include <cuda_bf16.h>
#include <math.h>
#include <stdint.h>

#define D_IN 1024
#define D_H  512
#define NBINS 10
#define MAXB 65536

// ---------------- scratch (no allocations allowed) ----------------
__device__ unsigned int g_min_enc[4];
__device__ unsigned int g_max_enc[4];
__device__ int          g_hist[4][NBINS];
__device__ float        g_wglobal[2];
__device__ __align__(16) __nv_bfloat16 g_W0hi[D_H * D_IN];
__device__ __align__(16) __nv_bfloat16 g_W0lo[D_H * D_IN];
__device__ __align__(16) float g_W1b[D_H];
__device__ __align__(16) float g_partial[2 * MAXB];

// ---------------- PTX helpers ----------------
__device__ __forceinline__ uint32_t smem_u32(const void* p) {
    uint32_t a;
    asm("{ .reg .u64 t; cvta.to.shared.u64 t, %1; cvt.u32.u64 %0, t; }"
        : "=r"(a) : "l"(p));
    return a;
}
__device__ __forceinline__ void cp16(uint32_t dst, const void* src) {
    asm volatile("cp.async.cg.shared.global [%0], [%1], 16;"
                 :: "r"(dst), "l"(src) : "memory");
}
__device__ __forceinline__ void cp_commit() {
    asm volatile("cp.async.commit_group;" ::: "memory");
}
template <int N>
__device__ __forceinline__ void cp_wait() {
    asm volatile("cp.async.wait_group %0;" :: "n"(N) : "memory");
}
__device__ __forceinline__ void ldsm4(uint32_t* r, uint32_t addr) {
    asm volatile("ldmatrix.sync.aligned.m8n8.x4.shared.b16 {%0,%1,%2,%3}, [%4];"
                 : "=r"(r[0]), "=r"(r[1]), "=r"(r[2]), "=r"(r[3]) : "r"(addr));
}
__device__ __forceinline__ void mma_bf16(float* c, const uint32_t* a,
                                         const uint32_t* b) {
    asm volatile(
        "mma.sync.aligned.m16n8k16.row.col.f32.bf16.bf16.f32 "
        "{%0,%1,%2,%3}, {%4,%5,%6,%7}, {%8,%9}, {%0,%1,%2,%3};"
        : "+f"(c[0]), "+f"(c[1]), "+f"(c[2]), "+f"(c[3])
        : "r"(a[0]), "r"(a[1]), "r"(a[2]), "r"(a[3]), "r"(b[0]), "r"(b[1]));
}
__device__ __forceinline__ void sts128(uint32_t addr, uint32_t a, uint32_t b,
                                       uint32_t c, uint32_t d) {
    asm volatile("st.shared.v4.b32 [%0], {%1,%2,%3,%4};"
                 :: "r"(addr), "r"(a), "r"(b), "r"(c), "r"(d) : "memory");
}

// ---------------- entropy path (exact jnp half-open bins) ----------
__device__ __forceinline__ unsigned int enc_f(float f) {
    unsigned int u = __float_as_uint(f);
    return (u & 0x80000000u) ? ~u : (u | 0x80000000u);
}
__device__ __forceinline__ float dec_f(unsigned int u) {
    u = (u & 0x80000000u) ? (u ^ 0x80000000u) : ~u;
    return __uint_as_float(u);
}

__global__ void init_kernel() {
    int t = threadIdx.x;
    if (t < 4) { g_min_enc[t] = 0xFFFFFFFFu; g_max_enc[t] = 0u; }
    if (t < 4 * NBINS) g_hist[t / NBINS][t % NBINS] = 0;
}

__global__ void minmax_kernel(const float* __restrict__ p, int n, int slot) {
    unsigned int mn = 0xFFFFFFFFu, mx = 0u;
    for (int i = blockIdx.x * blockDim.x + threadIdx.x; i < n;
         i += gridDim.x * blockDim.x) {
        unsigned int e = enc_f(p[i]);
        mn = min(mn, e); mx = max(mx, e);
    }
#pragma unroll
    for (int o = 16; o; o >>= 1) {
        mn = min(mn, __shfl_down_sync(0xffffffffu, mn, o));
        mx = max(mx, __shfl_down_sync(0xffffffffu, mx, o));
    }
    __shared__ unsigned int smn[8], smx[8];
    int w = threadIdx.x >> 5, l = threadIdx.x & 31;
    if (l == 0) { smn[w] = mn; smx[w] = mx; }
    __syncthreads();
    if (threadIdx.x == 0) {
        int nw = blockDim.x >> 5;
        for (int i = 1; i < nw; i++) { mn = min(mn, smn[i]); mx = max(mx, smx[i]); }
        atomicMin(&g_min_enc[slot], mn);
        atomicMax(&g_max_enc[slot], mx);
    }
}

__global__ void hist_kernel(const float* __restrict__ p, int n, int slot) {
    __shared__ int sh[NBINS];
    if (threadIdx.x < NBINS) sh[threadIdx.x] = 0;
    __syncthreads();
    float lo = dec_f(g_min_enc[slot]);
    float hi = dec_f(g_max_enc[slot]);
    float scale = __fdiv_rn(__fsub_rn(hi, lo), 10.0f);
    for (int i = blockIdx.x * blockDim.x + threadIdx.x; i < n;
         i += gridDim.x * blockDim.x) {
        float v = p[i];
#pragma unroll
        for (int b = 0; b < NBINS; b++) {
            float lower = __fadd_rn(lo, __fmul_rn((float)b, scale));
            float upper = __fadd_rn(lo, __fmul_rn((float)(b + 1), scale));
            if (v >= lower && v < upper) { atomicAdd(&sh[b], 1); break; }
        }
    }
    __syncthreads();
    if (threadIdx.x < NBINS) atomicAdd(&g_hist[slot][threadIdx.x], sh[threadIdx.x]);
}

__global__ void scalar_kernel() {
    if (threadIdx.x != 0) return;
    float H[4];
    const int ns[4] = {D_H * D_IN, D_H * D_IN, D_H, D_H};
    for (int a = 0; a < 4; a++) {
        float h = 0.f;
        for (int b = 0; b < NBINS; b++) {
            float pp = (float)g_hist[a][b] / (float)ns[a];
            if (pp > 0.f) h += -pp * logf(pp);
        }
        H[a] = h;
    }
    const float API = 0.12732395447351627f;  // 0.4/pi
    g_wglobal[0] = API * atanf(500.0f * (H[0] - H[1])) + 0.5f;
    g_wglobal[1] = API * atanf(500.0f * (H[2] - H[3])) + 0.5f;
}

__device__ __forceinline__ float blend_one(float base, float graft, float d, float wg) {
    float wl = 1.0f / (1.0f + expf(-d));
    float wb = wg * (1.0f - expf(-wg * wl));
    float og = 1.0f - wg;
    float wgf = og * (1.0f - expf(-og * (1.0f - wl)));
    float s = 1.0f / (1.0f + expf(wgf - wb));  // softmax pair == sigmoid(diff)
    return base * s + graft * (1.0f - s);
}

// d0 = |w0-g0| @ p0^T, fused blend epilogue -> split bf16 hi/lo
#define W0_BM 64
#define W0_BN 64
#define W0_BK 16
__global__ __launch_bounds__(256) void w0_blend_kernel(
    const float* __restrict__ w0, const float* __restrict__ g0,
    const float* __restrict__ p0) {
    __shared__ __align__(16) float As[W0_BK][W0_BM];
    __shared__ __align__(16) float Bs[W0_BK][W0_BN];
    int tid = threadIdx.x;
    int rowBase = blockIdx.y * W0_BM;  // over D_H
    int colBase = blockIdx.x * W0_BN;  // over D_IN
    int lr = tid >> 2;
    int lv = (tid & 3) * 4;
    int tr = tid >> 4, tc = tid & 15;
    float acc[4][4] = {};
    for (int kt = 0; kt < D_IN; kt += W0_BK) {
        float4 aw = *(const float4*)(w0 + (rowBase + lr) * D_IN + kt + lv);
        float4 ag = *(const float4*)(g0 + (rowBase + lr) * D_IN + kt + lv);
        float4 bb = *(const float4*)(p0 + (colBase + lr) * D_IN + kt + lv);
        __syncthreads();
        As[lv + 0][lr] = fabsf(aw.x - ag.x);
        As[lv + 1][lr] = fabsf(aw.y - ag.y);
        As[lv + 2][lr] = fabsf(aw.z - ag.z);
        As[lv + 3][lr] = fabsf(aw.w - ag.w);
        Bs[lv + 0][lr] = bb.x; Bs[lv + 1][lr] = bb.y;
        Bs[lv + 2][lr] = bb.z; Bs[lv + 3][lr] = bb.w;
        __syncthreads();
#pragma unroll
        for (int k = 0; k < W0_BK; k++) {
            float4 a = *(const float4*)&As[k][tr * 4];
            float4 b = *(const float4*)&Bs[k][tc * 4];
            float av[4] = {a.x, a.y, a.z, a.w};
            float bv[4] = {b.x, b.y, b.z, b.w};
#pragma unroll
            for (int i = 0; i < 4; i++)
#pragma unroll
                for (int j = 0; j < 4; j++) acc[i][j] += av[i] * bv[j];
        }
    }
    float wg = g_wglobal[0];
#pragma unroll
    for (int i = 0; i < 4; i++) {
        int o = rowBase + tr * 4 + i;
#pragma unroll
        for (int j = 0; j < 4; j++) {
            int c = colBase + tc * 4 + j;
            float v = blend_one(w0[o * D_IN + c], g0[o * D_IN + c], acc[i][j], wg);
            __nv_bfloat16 h = __float2bfloat16(v);
            __nv_bfloat16 l = __float2bfloat16(v - __bfloat162float(h));
            g_W0hi[o * D_IN + c] = h;
            g_W0lo[o * D_IN + c] = l;
        }
    }
}

__global__ void w1_blend_kernel(const float* __restrict__ w1,
                                const float* __restrict__ g1,
                                const float* __restrict__ p1) {
    int i = blockIdx.x * blockDim.x + threadIdx.x;
    if (i >= D_H) return;
    float d = 0.f;
    for (int k = 0; k < D_H; k++) d += fabsf(w1[k] - g1[k]) * p1[i * D_H + k];
    g_W1b[i] = blend_one(w1[i], g1[i], d, g_wglobal[1]);
}

// ---------------- main GEMM ---------------------------------------------
// CTA: M=128 x rows, N=256 hidden cols, K in 32-chunks (32 iters).
// Per chunk: x fp32 reg-prefetched -> split bf16 hi/lo -> smem (2 stages);
// B hi/lo via 3-stage cp.async ring; 3 mma sub-passes (hh, lo*hi, hi*lo).
// Epilogue fuses relu(h+b0) dot W1 -> partial per col-block.
#define GBM 128
#define GBN 256
#define GBK 32
#define KITER (D_IN / GBK)   // 32
#define ROWB 80              // padded row pitch in bytes (40 bf16)

#define A_OFF(st, hl) ((uint32_t)((st) * 20480 + (hl) * 10240))
#define B_OFF(st, hl) ((uint32_t)(40960 + (st) * 40960 + (hl) * 20480))
#define RED_OFF 163840u

__global__ __launch_bounds__(256, 1) void gemm_mma_kernel(
    const float* __restrict__ x, const float* __restrict__ b0, int Brows) {
    extern __shared__ char dsm[];
    const uint32_t sb = smem_u32(dsm);
    float* red = (float*)(dsm + RED_OFF);  // [128][4]

    const int tid = threadIdx.x;
    const int wid = tid >> 5, lane = tid & 31;
    const int wm = wid >> 2;       // 0..1  -> 64-row warp tile
    const int wn = wid & 3;        // 0..3  -> 64-col warp tile
    const int colBlk = blockIdx.x;            // 0..1
    const int rowBase = blockIdx.y * GBM;
    const int nBase = colBlk * GBN;

    // A-split thread mapping: row = tid>>1 (0..127), half = tid&1 (16 cols)
    const int ar = tid >> 1, ah = tid & 1;
    const float* xrow = x + (size_t)(rowBase + ar) * D_IN + ah * 16;

    float acc[4][8][4] = {};
    float4 xr[4];

    auto load_B = [&](int it, int st) {
        if (it < KITER) {
            const __nv_bfloat16* srcH = g_W0hi + (size_t)nBase * D_IN + it * GBK;
            const __nv_bfloat16* srcL = g_W0lo + (size_t)nBase * D_IN + it * GBK;
#pragma unroll
            for (int i = 0; i < 4; i++) {
                int q = tid + i * 256;          // 0..1023
                int r = q >> 2, g = q & 3;      // 256 rows x 4 granules
                uint32_t doff = (uint32_t)(r * ROWB + g * 16);
                cp16(sb + B_OFF(st, 0) + doff, srcH + (size_t)r * D_IN + g * 8);
                cp16(sb + B_OFF(st, 1) + doff, srcL + (size_t)r * D_IN + g * 8);
            }
        }
        cp_commit();
    };

    auto lds_x = [&](int it) {
        if (it < KITER) {
#pragma unroll
            for (int j = 0; j < 4; j++)
                xr[j] = *(const float4*)(xrow + it * GBK + j * 4);
        }
    };

    // split xr -> smem A stage (FIXED: separate staging arrays, no aliasing)
    auto sts_A = [&](int it) {
        if (it >= KITER) return;
        int st = it & 1;
        uint32_t hw[8], lw[8];
#pragma unroll
        for (int j = 0; j < 4; j++) {
            float v4[4] = {xr[j].x, xr[j].y, xr[j].z, xr[j].w};
            unsigned short hh[4], ll[4];
#pragma unroll
            for (int e = 0; e < 4; e++) {
                __nv_bfloat16 h = __float2bfloat16(v4[e]);
                __nv_bfloat16 l = __float2bfloat16(v4[e] - __bfloat162float(h));
                hh[e] = __bfloat16_as_ushort(h);
                ll[e] = __bfloat16_as_ushort(l);
            }
            hw[2 * j]     = (uint32_t)hh[0] | ((uint32_t)hh[1] << 16);
            hw[2 * j + 1] = (uint32_t)hh[2] | ((uint32_t)hh[3] << 16);
            lw[2 * j]     = (uint32_t)ll[0] | ((uint32_t)ll[1] << 16);
            lw[2 * j + 1] = (uint32_t)ll[2] | ((uint32_t)ll[3] << 16);
        }
        uint32_t base = (uint32_t)(ar * ROWB + ah * 32);
        sts128(sb + A_OFF(st, 0) + base,      hw[0], hw[1], hw[2], hw[3]);
        sts128(sb + A_OFF(st, 0) + base + 16, hw[4], hw[5], hw[6], hw[7]);
        sts128(sb + A_OFF(st, 1) + base,      lw[0], lw[1], lw[2], lw[3]);
        sts128(sb + A_OFF(st, 1) + base + 16, lw[4], lw[5], lw[6], lw[7]);
    };

    // prologue
    lds_x(0);
    sts_A(0);
    lds_x(1);
    load_B(0, 0);
    load_B(1, 1);

    for (int it = 0; it < KITER; ++it) {
        const int ast = it & 1;
        const int bst = it % 3;
        cp_wait<1>();
        __syncthreads();
        sts_A(it + 1);            // writes A stage (it+1)&1 — safe post-barrier
        lds_x(it + 2);            // prefetch x for chunk it+2
        load_B(it + 2, (it + 2) % 3);

        const uint32_t aHi = sb + A_OFF(ast, 0), aLo = sb + A_OFF(ast, 1);
        const uint32_t bHi = sb + B_OFF(bst, 0), bLo = sb + B_OFF(bst, 1);
#pragma unroll
        for (int ks = 0; ks < 2; ks++) {
            uint32_t a_hi[4][4], a_lo[4][4], b[4][4];
#pragma unroll
            for (int mi = 0; mi < 4; mi++) {
                uint32_t ro = (uint32_t)((wm * 64 + mi * 16 + (lane & 15)) * ROWB +
                                         ks * 32 + (lane >> 4) * 16);
                ldsm4(a_hi[mi], aHi + ro);
                ldsm4(a_lo[mi], aLo + ro);
            }
            uint32_t bo[4];
#pragma unroll
            for (int p = 0; p < 4; p++) {
                bo[p] = (uint32_t)((wn * 64 + p * 16 + (lane >> 4) * 8 + (lane & 7)) * ROWB +
                                   ks * 32 + ((lane >> 3) & 1) * 16);
                ldsm4(b[p], bHi + bo[p]);
            }
#pragma unroll
            for (int mi = 0; mi < 4; mi++)
#pragma unroll
                for (int p = 0; p < 4; p++) {
                    mma_bf16(acc[mi][2 * p],     a_hi[mi], &b[p][0]);
                    mma_bf16(acc[mi][2 * p + 1], a_hi[mi], &b[p][2]);
                    mma_bf16(acc[mi][2 * p],     a_lo[mi], &b[p][0]);
                    mma_bf16(acc[mi][2 * p + 1], a_lo[mi], &b[p][2]);
                }
#pragma unroll
            for (int p = 0; p < 4; p++) ldsm4(b[p], bLo + bo[p]);
#pragma unroll
            for (int mi = 0; mi < 4; mi++)
#pragma unroll
                for (int p = 0; p < 4; p++) {
                    mma_bf16(acc[mi][2 * p],     a_hi[mi], &b[p][0]);
                    mma_bf16(acc[mi][2 * p + 1], a_hi[mi], &b[p][2]);
                }
        }
    }

    // ---- epilogue: relu(acc + b0) dot W1 over this CTA's 256 hidden cols ----
    float w1v[8][2], b0v[8][2];
#pragma unroll
    for (int ni = 0; ni < 8; ni++) {
        int c = nBase + wn * 64 + ni * 8 + 2 * (lane & 3);
        w1v[ni][0] = g_W1b[c];      w1v[ni][1] = g_W1b[c + 1];
        b0v[ni][0] = __ldg(b0 + c); b0v[ni][1] = __ldg(b0 + c + 1);
    }
#pragma unroll
    for (int mi = 0; mi < 4; mi++) {
        float r0 = 0.f, r1 = 0.f;
#pragma unroll
        for (int ni = 0; ni < 8; ni++) {
            r0 += fmaxf(acc[mi][ni][0] + b0v[ni][0], 0.f) * w1v[ni][0];
            r0 += fmaxf(acc[mi][ni][1] + b0v[ni][1], 0.f) * w1v[ni][1];
            r1 += fmaxf(acc[mi][ni][2] + b0v[ni][0], 0.f) * w1v[ni][0];
            r1 += fmaxf(acc[mi][ni][3] + b0v[ni][1], 0.f) * w1v[ni][1];
        }
        r0 += __shfl_xor_sync(0xffffffffu, r0, 1);
        r0 += __shfl_xor_sync(0xffffffffu, r0, 2);
        r1 += __shfl_xor_sync(0xffffffffu, r1, 1);
        r1 += __shfl_xor_sync(0xffffffffu, r1, 2);
        if ((lane & 3) == 0) {
            int rr = wm * 64 + mi * 16 + (lane >> 2);
            red[rr * 4 + wn] = r0;
            red[(rr + 8) * 4 + wn] = r1;
        }
    }
    __syncthreads();
    if (tid < GBM) {
        float s = red[tid * 4] + red[tid * 4 + 1] + red[tid * 4 + 2] + red[tid * 4 + 3];
        g_partial[(size_t)colBlk * Brows + rowBase + tid] = s;
    }
}

__global__ void reduce_kernel(float* __restrict__ out, const float* __restrict__ b1,
                              int Brows) {
    int b = blockIdx.x * blockDim.x + threadIdx.x;
    if (b < Brows)
        out[b] = b1[0] + g_partial[b] + g_partial[(size_t)Brows + b];
}

extern "C" void kernel_launch(void* const* d_in, const int* in_sizes, int n_in,
                              void* d_out, int out_size) {
    const float* x  = (const float*)d_in[0];
    const float* w0 = (const float*)d_in[1];
    const float* b0 = (const float*)d_in[2];
    const float* w1 = (const float*)d_in[3];
    const float* b1 = (const float*)d_in[4];
    const float* p0 = (const float*)d_in[5];
    const float* p1 = (const float*)d_in[6];
    const float* g0 = (const float*)d_in[7];
    const float* g1 = (const float*)d_in[8];
    float* out = (float*)d_out;
    int Brows = in_sizes[0] / D_IN;
    const int nbig = D_H * D_IN;

    const int DYN = 166912;  // A 40960 + B 122880 + red 2048, padded
    cudaFuncSetAttribute(gemm_mma_kernel,
                         cudaFuncAttributeMaxDynamicSharedMemorySize, DYN);

    init_kernel<<<1, 64>>>();
    minmax_kernel<<<128, 256>>>(w0, nbig, 0);
    minmax_kernel<<<128, 256>>>(g0, nbig, 1);
    minmax_kernel<<<1, 256>>>(w1, D_H, 2);
    minmax_kernel<<<1, 256>>>(g1, D_H, 3);
    hist_kernel<<<128, 256>>>(w0, nbig, 0);
    hist_kernel<<<128, 256>>>(g0, nbig, 1);
    hist_kernel<<<1, 256>>>(w1, D_H, 2);
    hist_kernel<<<1, 256>>>(g1, D_H, 3);
    scalar_kernel<<<1, 32>>>();
    w0_blend_kernel<<<dim3(D_IN / W0_BN, D_H / W0_BM), 256>>>(w0, g0, p0);
    w1_blend_kernel<<<2, 256>>>(w1, g1, p1);
    gemm_mma_kernel<<<dim3(2, Brows / GBM), 256, DYN>>>(x, b0, Brows);
    reduce_kernel<<<(Brows + 255) / 256, 256>>>(out, b1, Brows);
}

// round 7
// speedup vs baseline: 2.8623x; 1.2432x over previous
#include <cuda_runtime.h>
#include <cuda_fp16.h>
#include <cuda_bf16.h>
#include <math.h>
#include <stdint.h>

#define D_IN 1024
#define D_H  512
#define NBINS 10
#define MAXB 65536

// ---------------- scratch (no allocations allowed) ----------------
__device__ unsigned int g_min_enc[4];
__device__ unsigned int g_max_enc[4];
__device__ int          g_hist[4][NBINS];
__device__ float        g_wglobal[2];
__device__ __align__(16) __half g_W0h[D_H * D_IN];   // blended W0, fp16
__device__ __align__(16) float g_W1b[D_H];
__device__ __align__(16) float g_partial[2 * MAXB];

// ---------------- PTX helpers ----------------
__device__ __forceinline__ uint32_t smem_u32(const void* p) {
    uint32_t a;
    asm("{ .reg .u64 t; cvta.to.shared.u64 t, %1; cvt.u32.u64 %0, t; }"
        : "=r"(a) : "l"(p));
    return a;
}
__device__ __forceinline__ void cp16(uint32_t dst, const void* src) {
    asm volatile("cp.async.cg.shared.global [%0], [%1], 16;"
                 :: "r"(dst), "l"(src) : "memory");
}
__device__ __forceinline__ void cp_commit() {
    asm volatile("cp.async.commit_group;" ::: "memory");
}
template <int N>
__device__ __forceinline__ void cp_wait() {
    asm volatile("cp.async.wait_group %0;" :: "n"(N) : "memory");
}
__device__ __forceinline__ void ldsm4(uint32_t* r, uint32_t addr) {
    asm volatile("ldmatrix.sync.aligned.m8n8.x4.shared.b16 {%0,%1,%2,%3}, [%4];"
                 : "=r"(r[0]), "=r"(r[1]), "=r"(r[2]), "=r"(r[3]) : "r"(addr));
}
__device__ __forceinline__ void mma_f16(float* c, const uint32_t* a,
                                        const uint32_t* b) {
    asm volatile(
        "mma.sync.aligned.m16n8k16.row.col.f32.f16.f16.f32 "
        "{%0,%1,%2,%3}, {%4,%5,%6,%7}, {%8,%9}, {%0,%1,%2,%3};"
        : "+f"(c[0]), "+f"(c[1]), "+f"(c[2]), "+f"(c[3])
        : "r"(a[0]), "r"(a[1]), "r"(a[2]), "r"(a[3]), "r"(b[0]), "r"(b[1]));
}
__device__ __forceinline__ void sts128(uint32_t addr, uint32_t a, uint32_t b,
                                       uint32_t c, uint32_t d) {
    asm volatile("st.shared.v4.b32 [%0], {%1,%2,%3,%4};"
                 :: "r"(addr), "r"(a), "r"(b), "r"(c), "r"(d) : "memory");
}

// ---------------- entropy path (exact jnp half-open bins) ----------
__device__ __forceinline__ unsigned int enc_f(float f) {
    unsigned int u = __float_as_uint(f);
    return (u & 0x80000000u) ? ~u : (u | 0x80000000u);
}
__device__ __forceinline__ float dec_f(unsigned int u) {
    u = (u & 0x80000000u) ? (u ^ 0x80000000u) : ~u;
    return __uint_as_float(u);
}

__global__ void init_kernel() {
    int t = threadIdx.x;
    if (t < 4) { g_min_enc[t] = 0xFFFFFFFFu; g_max_enc[t] = 0u; }
    if (t < 4 * NBINS) g_hist[t / NBINS][t % NBINS] = 0;
}

__global__ void minmax_kernel(const float* __restrict__ p, int n, int slot) {
    unsigned int mn = 0xFFFFFFFFu, mx = 0u;
    for (int i = blockIdx.x * blockDim.x + threadIdx.x; i < n;
         i += gridDim.x * blockDim.x) {
        unsigned int e = enc_f(p[i]);
        mn = min(mn, e); mx = max(mx, e);
    }
#pragma unroll
    for (int o = 16; o; o >>= 1) {
        mn = min(mn, __shfl_down_sync(0xffffffffu, mn, o));
        mx = max(mx, __shfl_down_sync(0xffffffffu, mx, o));
    }
    __shared__ unsigned int smn[8], smx[8];
    int w = threadIdx.x >> 5, l = threadIdx.x & 31;
    if (l == 0) { smn[w] = mn; smx[w] = mx; }
    __syncthreads();
    if (threadIdx.x == 0) {
        int nw = blockDim.x >> 5;
        for (int i = 1; i < nw; i++) { mn = min(mn, smn[i]); mx = max(mx, smx[i]); }
        atomicMin(&g_min_enc[slot], mn);
        atomicMax(&g_max_enc[slot], mx);
    }
}

__global__ void hist_kernel(const float* __restrict__ p, int n, int slot) {
    __shared__ int sh[NBINS];
    if (threadIdx.x < NBINS) sh[threadIdx.x] = 0;
    __syncthreads();
    float lo = dec_f(g_min_enc[slot]);
    float hi = dec_f(g_max_enc[slot]);
    float scale = __fdiv_rn(__fsub_rn(hi, lo), 10.0f);
    for (int i = blockIdx.x * blockDim.x + threadIdx.x; i < n;
         i += gridDim.x * blockDim.x) {
        float v = p[i];
#pragma unroll
        for (int b = 0; b < NBINS; b++) {
            float lower = __fadd_rn(lo, __fmul_rn((float)b, scale));
            float upper = __fadd_rn(lo, __fmul_rn((float)(b + 1), scale));
            if (v >= lower && v < upper) { atomicAdd(&sh[b], 1); break; }
        }
    }
    __syncthreads();
    if (threadIdx.x < NBINS) atomicAdd(&g_hist[slot][threadIdx.x], sh[threadIdx.x]);
}

__global__ void scalar_kernel() {
    if (threadIdx.x != 0) return;
    float H[4];
    const int ns[4] = {D_H * D_IN, D_H * D_IN, D_H, D_H};
    for (int a = 0; a < 4; a++) {
        float h = 0.f;
        for (int b = 0; b < NBINS; b++) {
            float pp = (float)g_hist[a][b] / (float)ns[a];
            if (pp > 0.f) h += -pp * logf(pp);
        }
        H[a] = h;
    }
    const float API = 0.12732395447351627f;  // 0.4/pi
    g_wglobal[0] = API * atanf(500.0f * (H[0] - H[1])) + 0.5f;
    g_wglobal[1] = API * atanf(500.0f * (H[2] - H[3])) + 0.5f;
}

__device__ __forceinline__ float blend_one(float base, float graft, float d, float wg) {
    float wl = 1.0f / (1.0f + expf(-d));
    float wb = wg * (1.0f - expf(-wg * wl));
    float og = 1.0f - wg;
    float wgf = og * (1.0f - expf(-og * (1.0f - wl)));
    float s = 1.0f / (1.0f + expf(wgf - wb));  // softmax pair == sigmoid(diff)
    return base * s + graft * (1.0f - s);
}

// d0 = |w0-g0| @ p0^T, fused blend epilogue -> fp16 W0
#define W0_BM 64
#define W0_BN 64
#define W0_BK 16
__global__ __launch_bounds__(256) void w0_blend_kernel(
    const float* __restrict__ w0, const float* __restrict__ g0,
    const float* __restrict__ p0) {
    __shared__ __align__(16) float As[W0_BK][W0_BM];
    __shared__ __align__(16) float Bs[W0_BK][W0_BN];
    int tid = threadIdx.x;
    int rowBase = blockIdx.y * W0_BM;  // over D_H
    int colBase = blockIdx.x * W0_BN;  // over D_IN
    int lr = tid >> 2;
    int lv = (tid & 3) * 4;
    int tr = tid >> 4, tc = tid & 15;
    float acc[4][4] = {};
    for (int kt = 0; kt < D_IN; kt += W0_BK) {
        float4 aw = *(const float4*)(w0 + (rowBase + lr) * D_IN + kt + lv);
        float4 ag = *(const float4*)(g0 + (rowBase + lr) * D_IN + kt + lv);
        float4 bb = *(const float4*)(p0 + (colBase + lr) * D_IN + kt + lv);
        __syncthreads();
        As[lv + 0][lr] = fabsf(aw.x - ag.x);
        As[lv + 1][lr] = fabsf(aw.y - ag.y);
        As[lv + 2][lr] = fabsf(aw.z - ag.z);
        As[lv + 3][lr] = fabsf(aw.w - ag.w);
        Bs[lv + 0][lr] = bb.x; Bs[lv + 1][lr] = bb.y;
        Bs[lv + 2][lr] = bb.z; Bs[lv + 3][lr] = bb.w;
        __syncthreads();
#pragma unroll
        for (int k = 0; k < W0_BK; k++) {
            float4 a = *(const float4*)&As[k][tr * 4];
            float4 b = *(const float4*)&Bs[k][tc * 4];
            float av[4] = {a.x, a.y, a.z, a.w};
            float bv[4] = {b.x, b.y, b.z, b.w};
#pragma unroll
            for (int i = 0; i < 4; i++)
#pragma unroll
                for (int j = 0; j < 4; j++) acc[i][j] += av[i] * bv[j];
        }
    }
    float wg = g_wglobal[0];
#pragma unroll
    for (int i = 0; i < 4; i++) {
        int o = rowBase + tr * 4 + i;
#pragma unroll
        for (int j = 0; j < 4; j++) {
            int c = colBase + tc * 4 + j;
            float v = blend_one(w0[o * D_IN + c], g0[o * D_IN + c], acc[i][j], wg);
            g_W0h[o * D_IN + c] = __float2half_rn(v);
        }
    }
}

__global__ void w1_blend_kernel(const float* __restrict__ w1,
                                const float* __restrict__ g1,
                                const float* __restrict__ p1) {
    int i = blockIdx.x * blockDim.x + threadIdx.x;
    if (i >= D_H) return;
    float d = 0.f;
    for (int k = 0; k < D_H; k++) d += fabsf(w1[k] - g1[k]) * p1[i * D_H + k];
    g_W1b[i] = blend_one(w1[i], g1[i], d, g_wglobal[1]);
}

// ---------------- main GEMM ---------------------------------------------
// CTA: M=128 x rows, N=256 hidden cols, K in 32-chunks (32 iters).
// fp16 2-pass: x split into fp16 hi+lo in-kernel; W0 single fp16.
// D = (xh + xl) @ W0h. Epilogue fuses relu(h+b0) dot W1 -> partial.
#define GBM 128
#define GBN 256
#define GBK 32
#define KITER (D_IN / GBK)   // 32
#define ROWB 80              // padded row pitch in bytes (40 fp16)

#define A_OFF(st, hl) ((uint32_t)((st) * 20480 + (hl) * 10240))
#define B_OFF(st) ((uint32_t)(40960 + (st) * 20480))
#define RED_OFF 102400u

__global__ __launch_bounds__(256, 1) void gemm_mma_kernel(
    const float* __restrict__ x, const float* __restrict__ b0, int Brows) {
    extern __shared__ char dsm[];
    const uint32_t sb = smem_u32(dsm);
    float* red = (float*)(dsm + RED_OFF);  // [128][4]

    const int tid = threadIdx.x;
    const int wid = tid >> 5, lane = tid & 31;
    const int wm = wid >> 2;       // 0..1  -> 64-row warp tile
    const int wn = wid & 3;        // 0..3  -> 64-col warp tile
    const int colBlk = blockIdx.x;            // 0..1
    const int rowBase = blockIdx.y * GBM;
    const int nBase = colBlk * GBN;

    // A-split thread mapping: row = tid>>1 (0..127), half = tid&1 (16 cols)
    const int ar = tid >> 1, ah = tid & 1;
    const float* xrow = x + (size_t)(rowBase + ar) * D_IN + ah * 16;

    float acc[4][8][4] = {};
    float4 xr[4];

    auto load_B = [&](int it, int st) {
        if (it < KITER) {
            const __half* srcH = g_W0h + (size_t)nBase * D_IN + it * GBK;
#pragma unroll
            for (int i = 0; i < 4; i++) {
                int q = tid + i * 256;          // 0..1023
                int r = q >> 2, g = q & 3;      // 256 rows x 4 granules
                uint32_t doff = (uint32_t)(r * ROWB + g * 16);
                cp16(sb + B_OFF(st) + doff, srcH + (size_t)r * D_IN + g * 8);
            }
        }
        cp_commit();
    };

    auto lds_x = [&](int it) {
        if (it < KITER) {
#pragma unroll
            for (int j = 0; j < 4; j++)
                xr[j] = *(const float4*)(xrow + it * GBK + j * 4);
        }
    };

    // split xr -> smem A stage (fp16 hi + fp16 residual lo)
    auto sts_A = [&](int it) {
        if (it >= KITER) return;
        int st = it & 1;
        uint32_t hw[8], lw[8];
#pragma unroll
        for (int j = 0; j < 4; j++) {
            float v4[4] = {xr[j].x, xr[j].y, xr[j].z, xr[j].w};
            unsigned short hh[4], ll[4];
#pragma unroll
            for (int e = 0; e < 4; e++) {
                __half h = __float2half_rn(v4[e]);
                __half l = __float2half_rn(v4[e] - __half2float(h));
                hh[e] = __half_as_ushort(h);
                ll[e] = __half_as_ushort(l);
            }
            hw[2 * j]     = (uint32_t)hh[0] | ((uint32_t)hh[1] << 16);
            hw[2 * j + 1] = (uint32_t)hh[2] | ((uint32_t)hh[3] << 16);
            lw[2 * j]     = (uint32_t)ll[0] | ((uint32_t)ll[1] << 16);
            lw[2 * j + 1] = (uint32_t)ll[2] | ((uint32_t)ll[3] << 16);
        }
        uint32_t base = (uint32_t)(ar * ROWB + ah * 32);
        sts128(sb + A_OFF(st, 0) + base,      hw[0], hw[1], hw[2], hw[3]);
        sts128(sb + A_OFF(st, 0) + base + 16, hw[4], hw[5], hw[6], hw[7]);
        sts128(sb + A_OFF(st, 1) + base,      lw[0], lw[1], lw[2], lw[3]);
        sts128(sb + A_OFF(st, 1) + base + 16, lw[4], lw[5], lw[6], lw[7]);
    };

    // prologue
    lds_x(0);
    sts_A(0);
    lds_x(1);
    load_B(0, 0);
    load_B(1, 1);

    for (int it = 0; it < KITER; ++it) {
        const int ast = it & 1;
        const int bst = it % 3;
        cp_wait<1>();
        __syncthreads();
        sts_A(it + 1);            // writes A stage (it+1)&1 — safe post-barrier
        lds_x(it + 2);            // prefetch x for chunk it+2
        load_B(it + 2, (it + 2) % 3);

        const uint32_t aHi = sb + A_OFF(ast, 0), aLo = sb + A_OFF(ast, 1);
        const uint32_t bS = sb + B_OFF(bst);
#pragma unroll
        for (int ks = 0; ks < 2; ks++) {
            uint32_t a_hi[4][4], a_lo[4][4], b[4][4];
#pragma unroll
            for (int mi = 0; mi < 4; mi++) {
                uint32_t ro = (uint32_t)((wm * 64 + mi * 16 + (lane & 15)) * ROWB +
                                         ks * 32 + (lane >> 4) * 16);
                ldsm4(a_hi[mi], aHi + ro);
                ldsm4(a_lo[mi], aLo + ro);
            }
#pragma unroll
            for (int p = 0; p < 4; p++) {
                uint32_t bo = (uint32_t)((wn * 64 + p * 16 + (lane >> 4) * 8 + (lane & 7)) * ROWB +
                                         ks * 32 + ((lane >> 3) & 1) * 16);
                ldsm4(b[p], bS + bo);
            }
#pragma unroll
            for (int mi = 0; mi < 4; mi++)
#pragma unroll
                for (int p = 0; p < 4; p++) {
                    mma_f16(acc[mi][2 * p],     a_hi[mi], &b[p][0]);
                    mma_f16(acc[mi][2 * p + 1], a_hi[mi], &b[p][2]);
                    mma_f16(acc[mi][2 * p],     a_lo[mi], &b[p][0]);
                    mma_f16(acc[mi][2 * p + 1], a_lo[mi], &b[p][2]);
                }
        }
    }

    // ---- epilogue: relu(acc + b0) dot W1 over this CTA's 256 hidden cols ----
    float w1v[8][2], b0v[8][2];
#pragma unroll
    for (int ni = 0; ni < 8; ni++) {
        int c = nBase + wn * 64 + ni * 8 + 2 * (lane & 3);
        w1v[ni][0] = g_W1b[c];      w1v[ni][1] = g_W1b[c + 1];
        b0v[ni][0] = __ldg(b0 + c); b0v[ni][1] = __ldg(b0 + c + 1);
    }
#pragma unroll
    for (int mi = 0; mi < 4; mi++) {
        float r0 = 0.f, r1 = 0.f;
#pragma unroll
        for (int ni = 0; ni < 8; ni++) {
            r0 += fmaxf(acc[mi][ni][0] + b0v[ni][0], 0.f) * w1v[ni][0];
            r0 += fmaxf(acc[mi][ni][1] + b0v[ni][1], 0.f) * w1v[ni][1];
            r1 += fmaxf(acc[mi][ni][2] + b0v[ni][0], 0.f) * w1v[ni][0];
            r1 += fmaxf(acc[mi][ni][3] + b0v[ni][1], 0.f) * w1v[ni][1];
        }
        r0 += __shfl_xor_sync(0xffffffffu, r0, 1);
        r0 += __shfl_xor_sync(0xffffffffu, r0, 2);
        r1 += __shfl_xor_sync(0xffffffffu, r1, 1);
        r1 += __shfl_xor_sync(0xffffffffu, r1, 2);
        if ((lane & 3) == 0) {
            int rr = wm * 64 + mi * 16 + (lane >> 2);
            red[rr * 4 + wn] = r0;
            red[(rr + 8) * 4 + wn] = r1;
        }
    }
    __syncthreads();
    if (tid < GBM) {
        float s = red[tid * 4] + red[tid * 4 + 1] + red[tid * 4 + 2] + red[tid * 4 + 3];
        g_partial[(size_t)colBlk * Brows + rowBase + tid] = s;
    }
}

__global__ void reduce_kernel(float* __restrict__ out, const float* __restrict__ b1,
                              int Brows) {
    int b = blockIdx.x * blockDim.x + threadIdx.x;
    if (b < Brows)
        out[b] = b1[0] + g_partial[b] + g_partial[(size_t)Brows + b];
}

extern "C" void kernel_launch(void* const* d_in, const int* in_sizes, int n_in,
                              void* d_out, int out_size) {
    const float* x  = (const float*)d_in[0];
    const float* w0 = (const float*)d_in[1];
    const float* b0 = (const float*)d_in[2];
    const float* w1 = (const float*)d_in[3];
    const float* b1 = (const float*)d_in[4];
    const float* p0 = (const float*)d_in[5];
    const float* p1 = (const float*)d_in[6];
    const float* g0 = (const float*)d_in[7];
    const float* g1 = (const float*)d_in[8];
    float* out = (float*)d_out;
    int Brows = in_sizes[0] / D_IN;
    const int nbig = D_H * D_IN;

    const int DYN = 104448;  // A 40960 + B 61440 + red 2048
    cudaFuncSetAttribute(gemm_mma_kernel,
                         cudaFuncAttributeMaxDynamicSharedMemorySize, DYN);

    init_kernel<<<1, 64>>>();
    minmax_kernel<<<128, 256>>>(w0, nbig, 0);
    minmax_kernel<<<128, 256>>>(g0, nbig, 1);
    minmax_kernel<<<1, 256>>>(w1, D_H, 2);
    minmax_kernel<<<1, 256>>>(g1, D_H, 3);
    hist_kernel<<<128, 256>>>(w0, nbig, 0);
    hist_kernel<<<128, 256>>>(g0, nbig, 1);
    hist_kernel<<<1, 256>>>(w1, D_H, 2);
    hist_kernel<<<1, 256>>>(g1, D_H, 3);
    scalar_kernel<<<1, 32>>>();
    w0_blend_kernel<<<dim3(D_IN / W0_BN, D_H / W0_BM), 256>>>(w0, g0, p0);
    w1_blend_kernel<<<2, 256>>>(w1, g1, p1);
    gemm_mma_kernel<<<dim3(2, Brows / GBM), 256, DYN>>>(x, b0, Brows);
    reduce_kernel<<<(Brows + 255) / 256, 256>>>(out, b1, Brows);
}

// round 8
// speedup vs baseline: 3.8851x; 1.3573x over previous
#include <cuda_runtime.h>
#include <cuda_fp16.h>
#include <math.h>
#include <stdint.h>

#define D_IN 1024
#define D_H  512
#define NBINS 10
#define MAXB 65536

// ---------------- scratch (no allocations allowed) ----------------
__device__ unsigned int g_min_enc[2];
__device__ unsigned int g_max_enc[2];
__device__ int          g_hist[2][NBINS];
__device__ float        g_wglobal[2];
__device__ __align__(16) __half g_W0h[D_H * D_IN];   // blended W0, fp16
__device__ __align__(16) float g_W1b[D_H];
__device__ __align__(16) float g_partial[2 * MAXB];

// ---------------- PTX helpers ----------------
__device__ __forceinline__ uint32_t smem_u32(const void* p) {
    uint32_t a;
    asm("{ .reg .u64 t; cvta.to.shared.u64 t, %1; cvt.u32.u64 %0, t; }"
        : "=r"(a) : "l"(p));
    return a;
}
__device__ __forceinline__ void cp16(uint32_t dst, const void* src) {
    asm volatile("cp.async.cg.shared.global [%0], [%1], 16;"
                 :: "r"(dst), "l"(src) : "memory");
}
__device__ __forceinline__ void cp_commit() {
    asm volatile("cp.async.commit_group;" ::: "memory");
}
template <int N>
__device__ __forceinline__ void cp_wait() {
    asm volatile("cp.async.wait_group %0;" :: "n"(N) : "memory");
}
__device__ __forceinline__ void ldsm4(uint32_t* r, uint32_t addr) {
    asm volatile("ldmatrix.sync.aligned.m8n8.x4.shared.b16 {%0,%1,%2,%3}, [%4];"
                 : "=r"(r[0]), "=r"(r[1]), "=r"(r[2]), "=r"(r[3]) : "r"(addr));
}
__device__ __forceinline__ void mma_f16(float* c, const uint32_t* a,
                                        const uint32_t* b) {
    asm volatile(
        "mma.sync.aligned.m16n8k16.row.col.f32.f16.f16.f32 "
        "{%0,%1,%2,%3}, {%4,%5,%6,%7}, {%8,%9}, {%0,%1,%2,%3};"
        : "+f"(c[0]), "+f"(c[1]), "+f"(c[2]), "+f"(c[3])
        : "r"(a[0]), "r"(a[1]), "r"(a[2]), "r"(a[3]), "r"(b[0]), "r"(b[1]));
}
__device__ __forceinline__ void sts128(uint32_t addr, uint32_t a, uint32_t b,
                                       uint32_t c, uint32_t d) {
    asm volatile("st.shared.v4.b32 [%0], {%1,%2,%3,%4};"
                 :: "r"(addr), "r"(a), "r"(b), "r"(c), "r"(d) : "memory");
}

// ---------------- entropy path (exact jnp half-open bins) ----------
__device__ __forceinline__ unsigned int enc_f(float f) {
    unsigned int u = __float_as_uint(f);
    return (u & 0x80000000u) ? ~u : (u | 0x80000000u);
}
__device__ __forceinline__ float dec_f(unsigned int u) {
    u = (u & 0x80000000u) ? (u ^ 0x80000000u) : ~u;
    return __uint_as_float(u);
}

__global__ void init_kernel() {
    int t = threadIdx.x;
    if (t < 2) { g_min_enc[t] = 0xFFFFFFFFu; g_max_enc[t] = 0u; }
    if (t < 2 * NBINS) g_hist[t / NBINS][t % NBINS] = 0;
}

__global__ void minmax_kernel(const float* __restrict__ p, int n, int slot) {
    unsigned int mn = 0xFFFFFFFFu, mx = 0u;
    for (int i = blockIdx.x * blockDim.x + threadIdx.x; i < n;
         i += gridDim.x * blockDim.x) {
        unsigned int e = enc_f(p[i]);
        mn = min(mn, e); mx = max(mx, e);
    }
#pragma unroll
    for (int o = 16; o; o >>= 1) {
        mn = min(mn, __shfl_down_sync(0xffffffffu, mn, o));
        mx = max(mx, __shfl_down_sync(0xffffffffu, mx, o));
    }
    __shared__ unsigned int smn[8], smx[8];
    int w = threadIdx.x >> 5, l = threadIdx.x & 31;
    if (l == 0) { smn[w] = mn; smx[w] = mx; }
    __syncthreads();
    if (threadIdx.x == 0) {
        int nw = blockDim.x >> 5;
        for (int i = 1; i < nw; i++) { mn = min(mn, smn[i]); mx = max(mx, smx[i]); }
        atomicMin(&g_min_enc[slot], mn);
        atomicMax(&g_max_enc[slot], mx);
    }
}

// big-array histogram: computed candidate bin, verified against the EXACT
// jnp bin-edge predicates (lower = lo + i*scale, no fma) — same result,
// ~3 compares instead of 10.
__global__ void hist_kernel(const float* __restrict__ p, int n, int slot) {
    __shared__ int sh[NBINS];
    if (threadIdx.x < NBINS) sh[threadIdx.x] = 0;
    __syncthreads();
    float lo = dec_f(g_min_enc[slot]);
    float hi = dec_f(g_max_enc[slot]);
    float scale = __fdiv_rn(__fsub_rn(hi, lo), 10.0f);
    float inv = 1.0f / scale;
    for (int i = blockIdx.x * blockDim.x + threadIdx.x; i < n;
         i += gridDim.x * blockDim.x) {
        float v = p[i];
        int bc = (int)((v - lo) * inv);
        int b0 = max(bc - 1, 0), b1 = min(bc + 1, NBINS - 1);
        for (int b = b0; b <= b1; b++) {
            float lower = __fadd_rn(lo, __fmul_rn((float)b, scale));
            float upper = __fadd_rn(lo, __fmul_rn((float)(b + 1), scale));
            if (v >= lower && v < upper) { atomicAdd(&sh[b], 1); break; }
        }
    }
    __syncthreads();
    if (threadIdx.x < NBINS) atomicAdd(&g_hist[slot][threadIdx.x], sh[threadIdx.x]);
}

// small-array (w1,g1: 512 elems) entropy + all scalar work in ONE kernel.
__global__ void scalar_kernel(const float* __restrict__ w1,
                              const float* __restrict__ g1) {
    __shared__ unsigned int smn[2], smx[2];
    __shared__ int shist[2][NBINS];
    __shared__ float sH[2];
    int tid = threadIdx.x;  // 256 threads
    if (tid < 2) { smn[tid] = 0xFFFFFFFFu; smx[tid] = 0u; }
    if (tid < 2 * NBINS) shist[tid / NBINS][tid % NBINS] = 0;
    __syncthreads();
    const float* arr[2] = {w1, g1};
    for (int a = 0; a < 2; a++) {
        float v0 = arr[a][tid], v1 = arr[a][tid + 256];
        unsigned int mn = min(enc_f(v0), enc_f(v1));
        unsigned int mx = max(enc_f(v0), enc_f(v1));
#pragma unroll
        for (int o = 16; o; o >>= 1) {
            mn = min(mn, __shfl_down_sync(0xffffffffu, mn, o));
            mx = max(mx, __shfl_down_sync(0xffffffffu, mx, o));
        }
        if ((tid & 31) == 0) { atomicMin(&smn[a], mn); atomicMax(&smx[a], mx); }
    }
    __syncthreads();
    for (int a = 0; a < 2; a++) {
        float lo = dec_f(smn[a]), hi = dec_f(smx[a]);
        float scale = __fdiv_rn(__fsub_rn(hi, lo), 10.0f);
#pragma unroll
        for (int e = 0; e < 2; e++) {
            float v = arr[a][tid + e * 256];
#pragma unroll
            for (int b = 0; b < NBINS; b++) {
                float lower = __fadd_rn(lo, __fmul_rn((float)b, scale));
                float upper = __fadd_rn(lo, __fmul_rn((float)(b + 1), scale));
                if (v >= lower && v < upper) { atomicAdd(&shist[a][b], 1); break; }
            }
        }
    }
    __syncthreads();
    if (tid == 0) {
        const float API = 0.12732395447351627f;  // 0.4/pi
        float Hbig[2];
        for (int a = 0; a < 2; a++) {
            float h = 0.f;
            for (int b = 0; b < NBINS; b++) {
                float pp = (float)g_hist[a][b] / (float)(D_H * D_IN);
                if (pp > 0.f) h += -pp * logf(pp);
            }
            Hbig[a] = h;
        }
        g_wglobal[0] = API * atanf(500.0f * (Hbig[0] - Hbig[1])) + 0.5f;
        for (int a = 0; a < 2; a++) {
            float h = 0.f;
            for (int b = 0; b < NBINS; b++) {
                float pp = (float)shist[a][b] / (float)D_H;
                if (pp > 0.f) h += -pp * logf(pp);
            }
            sH[a] = h;
        }
        g_wglobal[1] = API * atanf(500.0f * (sH[0] - sH[1])) + 0.5f;
    }
}

__device__ __forceinline__ float blend_one(float base, float graft, float d, float wg) {
    float wl = 1.0f / (1.0f + expf(-d));
    float wb = wg * (1.0f - expf(-wg * wl));
    float og = 1.0f - wg;
    float wgf = og * (1.0f - expf(-og * (1.0f - wl)));
    float s = 1.0f / (1.0f + expf(wgf - wb));  // softmax pair == sigmoid(diff)
    return base * s + graft * (1.0f - s);
}

// d0 = |w0-g0| @ p0^T, fused blend epilogue -> fp16 W0
#define W0_BM 64
#define W0_BN 64
#define W0_BK 16
__global__ __launch_bounds__(256) void w0_blend_kernel(
    const float* __restrict__ w0, const float* __restrict__ g0,
    const float* __restrict__ p0) {
    __shared__ __align__(16) float As[W0_BK][W0_BM];
    __shared__ __align__(16) float Bs[W0_BK][W0_BN];
    int tid = threadIdx.x;
    int rowBase = blockIdx.y * W0_BM;  // over D_H
    int colBase = blockIdx.x * W0_BN;  // over D_IN
    int lr = tid >> 2;
    int lv = (tid & 3) * 4;
    int tr = tid >> 4, tc = tid & 15;
    float acc[4][4] = {};
    for (int kt = 0; kt < D_IN; kt += W0_BK) {
        float4 aw = *(const float4*)(w0 + (rowBase + lr) * D_IN + kt + lv);
        float4 ag = *(const float4*)(g0 + (rowBase + lr) * D_IN + kt + lv);
        float4 bb = *(const float4*)(p0 + (colBase + lr) * D_IN + kt + lv);
        __syncthreads();
        As[lv + 0][lr] = fabsf(aw.x - ag.x);
        As[lv + 1][lr] = fabsf(aw.y - ag.y);
        As[lv + 2][lr] = fabsf(aw.z - ag.z);
        As[lv + 3][lr] = fabsf(aw.w - ag.w);
        Bs[lv + 0][lr] = bb.x; Bs[lv + 1][lr] = bb.y;
        Bs[lv + 2][lr] = bb.z; Bs[lv + 3][lr] = bb.w;
        __syncthreads();
#pragma unroll
        for (int k = 0; k < W0_BK; k++) {
            float4 a = *(const float4*)&As[k][tr * 4];
            float4 b = *(const float4*)&Bs[k][tc * 4];
            float av[4] = {a.x, a.y, a.z, a.w};
            float bv[4] = {b.x, b.y, b.z, b.w};
#pragma unroll
            for (int i = 0; i < 4; i++)
#pragma unroll
                for (int j = 0; j < 4; j++) acc[i][j] += av[i] * bv[j];
        }
    }
    float wg = g_wglobal[0];
#pragma unroll
    for (int i = 0; i < 4; i++) {
        int o = rowBase + tr * 4 + i;
#pragma unroll
        for (int j = 0; j < 4; j++) {
            int c = colBase + tc * 4 + j;
            float v = blend_one(w0[o * D_IN + c], g0[o * D_IN + c], acc[i][j], wg);
            g_W0h[o * D_IN + c] = __float2half_rn(v);
        }
    }
}

__global__ void w1_blend_kernel(const float* __restrict__ w1,
                                const float* __restrict__ g1,
                                const float* __restrict__ p1) {
    int i = blockIdx.x * blockDim.x + threadIdx.x;
    if (i >= D_H) return;
    float d = 0.f;
    for (int k = 0; k < D_H; k++) d += fabsf(w1[k] - g1[k]) * p1[i * D_H + k];
    g_W1b[i] = blend_one(w1[i], g1[i], d, g_wglobal[1]);
}

// ---------------- main GEMM ---------------------------------------------
// CTA: M=128 x rows, N=256 hidden cols, K in 32-chunks (32 iters).
// Single-pass fp16: x converted to fp16 in-kernel; W0 fp16.
// Epilogue fuses relu(h+b0) dot W1 -> partial per col-block.
#define GBM 128
#define GBN 256
#define GBK 32
#define KITER (D_IN / GBK)   // 32
#define ROWB 80              // padded row pitch in bytes (40 fp16)

#define A_OFF(st) ((uint32_t)((st) * 10240))
#define B_OFF(st) ((uint32_t)(20480 + (st) * 20480))
#define RED_OFF 81920u

__global__ __launch_bounds__(256, 1) void gemm_mma_kernel(
    const float* __restrict__ x, const float* __restrict__ b0, int Brows) {
    extern __shared__ char dsm[];
    const uint32_t sb = smem_u32(dsm);
    float* red = (float*)(dsm + RED_OFF);  // [128][4]

    const int tid = threadIdx.x;
    const int wid = tid >> 5, lane = tid & 31;
    const int wm = wid >> 2;       // 0..1  -> 64-row warp tile
    const int wn = wid & 3;        // 0..3  -> 64-col warp tile
    const int colBlk = blockIdx.x;            // 0..1
    const int rowBase = blockIdx.y * GBM;
    const int nBase = colBlk * GBN;

    // A thread mapping: row = tid>>1 (0..127), half = tid&1 (16 cols)
    const int ar = tid >> 1, ah = tid & 1;
    const float* xrow = x + (size_t)(rowBase + ar) * D_IN + ah * 16;

    float acc[4][8][4] = {};
    float4 xr[4];

    auto load_B = [&](int it, int st) {
        if (it < KITER) {
            const __half* srcH = g_W0h + (size_t)nBase * D_IN + it * GBK;
#pragma unroll
            for (int i = 0; i < 4; i++) {
                int q = tid + i * 256;          // 0..1023
                int r = q >> 2, g = q & 3;      // 256 rows x 4 granules
                uint32_t doff = (uint32_t)(r * ROWB + g * 16);
                cp16(sb + B_OFF(st) + doff, srcH + (size_t)r * D_IN + g * 8);
            }
        }
        cp_commit();
    };

    auto lds_x = [&](int it) {
        if (it < KITER) {
#pragma unroll
            for (int j = 0; j < 4; j++)
                xr[j] = *(const float4*)(xrow + it * GBK + j * 4);
        }
    };

    // convert xr -> fp16 -> smem A stage
    auto sts_A = [&](int it) {
        if (it >= KITER) return;
        int st = it & 1;
        uint32_t hw[8];
#pragma unroll
        for (int j = 0; j < 4; j++) {
            float v4[4] = {xr[j].x, xr[j].y, xr[j].z, xr[j].w};
            unsigned short hh[4];
#pragma unroll
            for (int e = 0; e < 4; e++)
                hh[e] = __half_as_ushort(__float2half_rn(v4[e]));
            hw[2 * j]     = (uint32_t)hh[0] | ((uint32_t)hh[1] << 16);
            hw[2 * j + 1] = (uint32_t)hh[2] | ((uint32_t)hh[3] << 16);
        }
        uint32_t base = (uint32_t)(ar * ROWB + ah * 32);
        sts128(sb + A_OFF(st) + base,      hw[0], hw[1], hw[2], hw[3]);
        sts128(sb + A_OFF(st) + base + 16, hw[4], hw[5], hw[6], hw[7]);
    };

    // prologue
    lds_x(0);
    sts_A(0);
    lds_x(1);
    load_B(0, 0);
    load_B(1, 1);

    for (int it = 0; it < KITER; ++it) {
        const int ast = it & 1;
        const int bst = it % 3;
        cp_wait<1>();
        __syncthreads();
        sts_A(it + 1);            // writes A stage (it+1)&1 — safe post-barrier
        lds_x(it + 2);            // prefetch x for chunk it+2
        load_B(it + 2, (it + 2) % 3);

        const uint32_t aS = sb + A_OFF(ast);
        const uint32_t bS = sb + B_OFF(bst);
#pragma unroll
        for (int ks = 0; ks < 2; ks++) {
            uint32_t a[4][4], b[4][4];
#pragma unroll
            for (int mi = 0; mi < 4; mi++) {
                uint32_t ro = (uint32_t)((wm * 64 + mi * 16 + (lane & 15)) * ROWB +
                                         ks * 32 + (lane >> 4) * 16);
                ldsm4(a[mi], aS + ro);
            }
#pragma unroll
            for (int p = 0; p < 4; p++) {
                uint32_t bo = (uint32_t)((wn * 64 + p * 16 + (lane >> 4) * 8 + (lane & 7)) * ROWB +
                                         ks * 32 + ((lane >> 3) & 1) * 16);
                ldsm4(b[p], bS + bo);
            }
#pragma unroll
            for (int mi = 0; mi < 4; mi++)
#pragma unroll
                for (int p = 0; p < 4; p++) {
                    mma_f16(acc[mi][2 * p],     a[mi], &b[p][0]);
                    mma_f16(acc[mi][2 * p + 1], a[mi], &b[p][2]);
                }
        }
    }

    // ---- epilogue: relu(acc + b0) dot W1 over this CTA's 256 hidden cols ----
    float w1v[8][2], b0v[8][2];
#pragma unroll
    for (int ni = 0; ni < 8; ni++) {
        int c = nBase + wn * 64 + ni * 8 + 2 * (lane & 3);
        w1v[ni][0] = g_W1b[c];      w1v[ni][1] = g_W1b[c + 1];
        b0v[ni][0] = __ldg(b0 + c); b0v[ni][1] = __ldg(b0 + c + 1);
    }
#pragma unroll
    for (int mi = 0; mi < 4; mi++) {
        float r0 = 0.f, r1 = 0.f;
#pragma unroll
        for (int ni = 0; ni < 8; ni++) {
            r0 += fmaxf(acc[mi][ni][0] + b0v[ni][0], 0.f) * w1v[ni][0];
            r0 += fmaxf(acc[mi][ni][1] + b0v[ni][1], 0.f) * w1v[ni][1];
            r1 += fmaxf(acc[mi][ni][2] + b0v[ni][0], 0.f) * w1v[ni][0];
            r1 += fmaxf(acc[mi][ni][3] + b0v[ni][1], 0.f) * w1v[ni][1];
        }
        r0 += __shfl_xor_sync(0xffffffffu, r0, 1);
        r0 += __shfl_xor_sync(0xffffffffu, r0, 2);
        r1 += __shfl_xor_sync(0xffffffffu, r1, 1);
        r1 += __shfl_xor_sync(0xffffffffu, r1, 2);
        if ((lane & 3) == 0) {
            int rr = wm * 64 + mi * 16 + (lane >> 2);
            red[rr * 4 + wn] = r0;
            red[(rr + 8) * 4 + wn] = r1;
        }
    }
    __syncthreads();
    if (tid < GBM) {
        float s = red[tid * 4] + red[tid * 4 + 1] + red[tid * 4 + 2] + red[tid * 4 + 3];
        g_partial[(size_t)colBlk * Brows + rowBase + tid] = s;
    }
}

__global__ void reduce_kernel(float* __restrict__ out, const float* __restrict__ b1,
                              int Brows) {
    int b = blockIdx.x * blockDim.x + threadIdx.x;
    if (b < Brows)
        out[b] = b1[0] + g_partial[b] + g_partial[(size_t)Brows + b];
}

extern "C" void kernel_launch(void* const* d_in, const int* in_sizes, int n_in,
                              void* d_out, int out_size) {
    const float* x  = (const float*)d_in[0];
    const float* w0 = (const float*)d_in[1];
    const float* b0 = (const float*)d_in[2];
    const float* w1 = (const float*)d_in[3];
    const float* b1 = (const float*)d_in[4];
    const float* p0 = (const float*)d_in[5];
    const float* p1 = (const float*)d_in[6];
    const float* g0 = (const float*)d_in[7];
    const float* g1 = (const float*)d_in[8];
    float* out = (float*)d_out;
    int Brows = in_sizes[0] / D_IN;
    const int nbig = D_H * D_IN;

    const int DYN = 83968;  // A 20480 + B 61440 + red 2048
    cudaFuncSetAttribute(gemm_mma_kernel,
                         cudaFuncAttributeMaxDynamicSharedMemorySize, DYN);

    init_kernel<<<1, 32>>>();
    minmax_kernel<<<128, 256>>>(w0, nbig, 0);
    minmax_kernel<<<128, 256>>>(g0, nbig, 1);
    hist_kernel<<<128, 256>>>(w0, nbig, 0);
    hist_kernel<<<128, 256>>>(g0, nbig, 1);
    scalar_kernel<<<1, 256>>>(w1, g1);
    w0_blend_kernel<<<dim3(D_IN / W0_BN, D_H / W0_BM), 256>>>(w0, g0, p0);
    w1_blend_kernel<<<2, 256>>>(w1, g1, p1);
    gemm_mma_kernel<<<dim3(2, Brows / GBM), 256, DYN>>>(x, b0, Brows);
    reduce_kernel<<<(Brows + 255) / 256, 256>>>(out, b1, Brows);
}

// round 9
// speedup vs baseline: 4.3686x; 1.1245x over previous
#include <cuda_runtime.h>
#include <cuda_fp16.h>
#include <math.h>
#include <stdint.h>

#define D_IN 1024
#define D_H  512
#define NBINS 10
#define MAXB 65536

// ---------------- scratch (no allocations allowed) ----------------
__device__ unsigned int g_min_enc[2];
__device__ unsigned int g_max_enc[2];
__device__ int          g_hist[2][NBINS];
__device__ float        g_wglobal[2];
__device__ __align__(16) __half g_W0h[D_H * D_IN];   // blended W0, fp16
__device__ __align__(16) float g_W1b[D_H];
__device__ __align__(16) float g_partial[2 * MAXB];

// ---------------- PTX helpers ----------------
__device__ __forceinline__ uint32_t smem_u32(const void* p) {
    uint32_t a;
    asm("{ .reg .u64 t; cvta.to.shared.u64 t, %1; cvt.u32.u64 %0, t; }"
        : "=r"(a) : "l"(p));
    return a;
}
__device__ __forceinline__ void cp16(uint32_t dst, const void* src) {
    asm volatile("cp.async.cg.shared.global [%0], [%1], 16;"
                 :: "r"(dst), "l"(src) : "memory");
}
__device__ __forceinline__ void cp_commit() {
    asm volatile("cp.async.commit_group;" ::: "memory");
}
template <int N>
__device__ __forceinline__ void cp_wait() {
    asm volatile("cp.async.wait_group %0;" :: "n"(N) : "memory");
}
__device__ __forceinline__ void ldsm4(uint32_t* r, uint32_t addr) {
    asm volatile("ldmatrix.sync.aligned.m8n8.x4.shared.b16 {%0,%1,%2,%3}, [%4];"
                 : "=r"(r[0]), "=r"(r[1]), "=r"(r[2]), "=r"(r[3]) : "r"(addr));
}
__device__ __forceinline__ void mma_f16(float* c, const uint32_t* a,
                                        const uint32_t* b) {
    asm volatile(
        "mma.sync.aligned.m16n8k16.row.col.f32.f16.f16.f32 "
        "{%0,%1,%2,%3}, {%4,%5,%6,%7}, {%8,%9}, {%0,%1,%2,%3};"
        : "+f"(c[0]), "+f"(c[1]), "+f"(c[2]), "+f"(c[3])
        : "r"(a[0]), "r"(a[1]), "r"(a[2]), "r"(a[3]), "r"(b[0]), "r"(b[1]));
}
__device__ __forceinline__ void sts128(uint32_t addr, uint32_t a, uint32_t b,
                                       uint32_t c, uint32_t d) {
    asm volatile("st.shared.v4.b32 [%0], {%1,%2,%3,%4};"
                 :: "r"(addr), "r"(a), "r"(b), "r"(c), "r"(d) : "memory");
}

// ---------------- entropy path (exact jnp half-open bins) ----------
__device__ __forceinline__ unsigned int enc_f(float f) {
    unsigned int u = __float_as_uint(f);
    return (u & 0x80000000u) ? ~u : (u | 0x80000000u);
}
__device__ __forceinline__ float dec_f(unsigned int u) {
    u = (u & 0x80000000u) ? (u ^ 0x80000000u) : ~u;
    return __uint_as_float(u);
}

__global__ void init_kernel() {
    int t = threadIdx.x;
    if (t < 2) { g_min_enc[t] = 0xFFFFFFFFu; g_max_enc[t] = 0u; }
    if (t < 2 * NBINS) g_hist[t / NBINS][t % NBINS] = 0;
}

// grid (G, 2): y picks array; float4 loads
__global__ void minmax2_kernel(const float* __restrict__ w0,
                               const float* __restrict__ g0, int n4) {
    int slot = blockIdx.y;
    const float4* p = (const float4*)(slot ? g0 : w0);
    unsigned int mn = 0xFFFFFFFFu, mx = 0u;
    int stride = gridDim.x * blockDim.x;
    for (int i = blockIdx.x * blockDim.x + threadIdx.x; i < n4; i += stride) {
        float4 v = p[i];
        unsigned int e0 = enc_f(v.x), e1 = enc_f(v.y);
        unsigned int e2 = enc_f(v.z), e3 = enc_f(v.w);
        mn = min(min(mn, e0), min(e1, min(e2, e3)));
        mx = max(max(mx, e0), max(e1, max(e2, e3)));
    }
#pragma unroll
    for (int o = 16; o; o >>= 1) {
        mn = min(mn, __shfl_down_sync(0xffffffffu, mn, o));
        mx = max(mx, __shfl_down_sync(0xffffffffu, mx, o));
    }
    __shared__ unsigned int smn[8], smx[8];
    int w = threadIdx.x >> 5, l = threadIdx.x & 31;
    if (l == 0) { smn[w] = mn; smx[w] = mx; }
    __syncthreads();
    if (threadIdx.x == 0) {
        int nw = blockDim.x >> 5;
        for (int i = 1; i < nw; i++) { mn = min(mn, smn[i]); mx = max(mx, smx[i]); }
        atomicMin(&g_min_enc[slot], mn);
        atomicMax(&g_max_enc[slot], mx);
    }
}

// candidate-bin histogram with EXACT jnp edge predicates; float4 loads
__global__ void hist2_kernel(const float* __restrict__ w0,
                             const float* __restrict__ g0, int n4) {
    int slot = blockIdx.y;
    const float4* p = (const float4*)(slot ? g0 : w0);
    __shared__ int sh[NBINS];
    if (threadIdx.x < NBINS) sh[threadIdx.x] = 0;
    __syncthreads();
    float lo = dec_f(g_min_enc[slot]);
    float hi = dec_f(g_max_enc[slot]);
    float scale = __fdiv_rn(__fsub_rn(hi, lo), 10.0f);
    float inv = 1.0f / scale;
    int stride = gridDim.x * blockDim.x;
    for (int i = blockIdx.x * blockDim.x + threadIdx.x; i < n4; i += stride) {
        float4 q = p[i];
        float vv[4] = {q.x, q.y, q.z, q.w};
#pragma unroll
        for (int e = 0; e < 4; e++) {
            float v = vv[e];
            int bc = (int)((v - lo) * inv);
            int b0 = max(bc - 1, 0), b1 = min(bc + 1, NBINS - 1);
            for (int b = b0; b <= b1; b++) {
                float lower = __fadd_rn(lo, __fmul_rn((float)b, scale));
                float upper = __fadd_rn(lo, __fmul_rn((float)(b + 1), scale));
                if (v >= lower && v < upper) { atomicAdd(&sh[b], 1); break; }
            }
        }
    }
    __syncthreads();
    if (threadIdx.x < NBINS) atomicAdd(&g_hist[slot][threadIdx.x], sh[threadIdx.x]);
}

// small-array (w1,g1) entropy + all scalar work in ONE kernel.
__global__ void scalar_kernel(const float* __restrict__ w1,
                              const float* __restrict__ g1) {
    __shared__ unsigned int smn[2], smx[2];
    __shared__ int shist[2][NBINS];
    __shared__ float sH[2];
    int tid = threadIdx.x;  // 256 threads
    if (tid < 2) { smn[tid] = 0xFFFFFFFFu; smx[tid] = 0u; }
    if (tid < 2 * NBINS) shist[tid / NBINS][tid % NBINS] = 0;
    __syncthreads();
    const float* arr[2] = {w1, g1};
    for (int a = 0; a < 2; a++) {
        float v0 = arr[a][tid], v1 = arr[a][tid + 256];
        unsigned int mn = min(enc_f(v0), enc_f(v1));
        unsigned int mx = max(enc_f(v0), enc_f(v1));
#pragma unroll
        for (int o = 16; o; o >>= 1) {
            mn = min(mn, __shfl_down_sync(0xffffffffu, mn, o));
            mx = max(mx, __shfl_down_sync(0xffffffffu, mx, o));
        }
        if ((tid & 31) == 0) { atomicMin(&smn[a], mn); atomicMax(&smx[a], mx); }
    }
    __syncthreads();
    for (int a = 0; a < 2; a++) {
        float lo = dec_f(smn[a]), hi = dec_f(smx[a]);
        float scale = __fdiv_rn(__fsub_rn(hi, lo), 10.0f);
#pragma unroll
        for (int e = 0; e < 2; e++) {
            float v = arr[a][tid + e * 256];
#pragma unroll
            for (int b = 0; b < NBINS; b++) {
                float lower = __fadd_rn(lo, __fmul_rn((float)b, scale));
                float upper = __fadd_rn(lo, __fmul_rn((float)(b + 1), scale));
                if (v >= lower && v < upper) { atomicAdd(&shist[a][b], 1); break; }
            }
        }
    }
    __syncthreads();
    if (tid == 0) {
        const float API = 0.12732395447351627f;  // 0.4/pi
        float Hbig[2];
        for (int a = 0; a < 2; a++) {
            float h = 0.f;
            for (int b = 0; b < NBINS; b++) {
                float pp = (float)g_hist[a][b] / (float)(D_H * D_IN);
                if (pp > 0.f) h += -pp * logf(pp);
            }
            Hbig[a] = h;
        }
        g_wglobal[0] = API * atanf(500.0f * (Hbig[0] - Hbig[1])) + 0.5f;
        for (int a = 0; a < 2; a++) {
            float h = 0.f;
            for (int b = 0; b < NBINS; b++) {
                float pp = (float)shist[a][b] / (float)D_H;
                if (pp > 0.f) h += -pp * logf(pp);
            }
            sH[a] = h;
        }
        g_wglobal[1] = API * atanf(500.0f * (sH[0] - sH[1])) + 0.5f;
    }
}

__device__ __forceinline__ float blend_one(float base, float graft, float d, float wg) {
    float wl = 1.0f / (1.0f + expf(-d));
    float wb = wg * (1.0f - expf(-wg * wl));
    float og = 1.0f - wg;
    float wgf = og * (1.0f - expf(-og * (1.0f - wl)));
    float s = 1.0f / (1.0f + expf(wgf - wb));  // softmax pair == sigmoid(diff)
    return base * s + graft * (1.0f - s);
}

// ---------- w0 blend via fp16 mma: d = |w0-g0| @ p0^T, epilogue -> g_W0h ----
// Tile: 64 rows x 128 cols, K-chunks of 32, 256 threads, LDG->cvt->STS.
#define WBROWB 80
__global__ __launch_bounds__(256) void w0_blend_mma_kernel(
    const float* __restrict__ w0, const float* __restrict__ g0,
    const float* __restrict__ p0) {
    __shared__ __align__(16) __half sA[2][64 * 40];
    __shared__ __align__(16) __half sB[2][128 * 40];
    const int tid = threadIdx.x;
    const int wid = tid >> 5, lane = tid & 31;
    const int wm = wid >> 2;   // 0..1 -> 32-row warp tile
    const int wn = wid & 3;    // 0..3 -> 32-col warp tile
    const int rowBase = blockIdx.y * 64;    // D_H/64 = 8
    const int colBase = blockIdx.x * 128;   // D_IN/128 = 8
    const uint32_t sAu = smem_u32(&sA[0][0]);
    const uint32_t sBu = smem_u32(&sB[0][0]);

    const int ar = tid >> 2, agr = tid & 3;     // A: 64 rows x 4 groups of 8
    const int br = tid >> 1, bh = tid & 1;      // B: 128 rows x 2 halves of 16

    float4 aw[2], ag[2], bp[4];
    float acc[2][4][4] = {};

    auto lds = [&](int it) {
        if (it < 32) {
            const float* wr = w0 + (size_t)(rowBase + ar) * D_IN + it * 32 + agr * 8;
            const float* gr = g0 + (size_t)(rowBase + ar) * D_IN + it * 32 + agr * 8;
            const float* pr = p0 + (size_t)(colBase + br) * D_IN + it * 32 + bh * 16;
#pragma unroll
            for (int j = 0; j < 2; j++) {
                aw[j] = *(const float4*)(wr + j * 4);
                ag[j] = *(const float4*)(gr + j * 4);
            }
#pragma unroll
            for (int j = 0; j < 4; j++) bp[j] = *(const float4*)(pr + j * 4);
        }
    };
    auto sts = [&](int it) {
        if (it >= 32) return;
        int st = it & 1;
        uint32_t wa[2];
#pragma unroll
        for (int j = 0; j < 2; j++) {
            float d0 = fabsf(aw[j].x - ag[j].x), d1 = fabsf(aw[j].y - ag[j].y);
            float d2 = fabsf(aw[j].z - ag[j].z), d3 = fabsf(aw[j].w - ag[j].w);
            unsigned short h0 = __half_as_ushort(__float2half_rn(d0));
            unsigned short h1 = __half_as_ushort(__float2half_rn(d1));
            unsigned short h2 = __half_as_ushort(__float2half_rn(d2));
            unsigned short h3 = __half_as_ushort(__float2half_rn(d3));
            wa[0] = (uint32_t)h0 | ((uint32_t)h1 << 16);
            wa[1] = (uint32_t)h2 | ((uint32_t)h3 << 16);
            if (j == 0) {
                // stash; stored with j==1's words below
                acc[0][0][0] += 0.f;  // no-op
            }
            if (j == 0) { /* keep in wa via separate vars */ }
            if (j == 0) { ((uint32_t*)&aw[0])[0] = wa[0]; ((uint32_t*)&aw[0])[1] = wa[1]; }
        }
        // rebuild: first 4 words from j=0 (stashed) + j=1 (in wa)
        uint32_t w0a = ((uint32_t*)&aw[0])[0], w1a = ((uint32_t*)&aw[0])[1];
        sts128(sAu + (uint32_t)(st * 5120 + ar * WBROWB + agr * 16),
               w0a, w1a, wa[0], wa[1]);
        uint32_t bw[8];
#pragma unroll
        for (int j = 0; j < 4; j++) {
            unsigned short h0 = __half_as_ushort(__float2half_rn(bp[j].x));
            unsigned short h1 = __half_as_ushort(__float2half_rn(bp[j].y));
            unsigned short h2 = __half_as_ushort(__float2half_rn(bp[j].z));
            unsigned short h3 = __half_as_ushort(__float2half_rn(bp[j].w));
            bw[2 * j]     = (uint32_t)h0 | ((uint32_t)h1 << 16);
            bw[2 * j + 1] = (uint32_t)h2 | ((uint32_t)h3 << 16);
        }
        uint32_t bb = sBu + (uint32_t)(st * 10240 + br * WBROWB + bh * 32);
        sts128(bb,      bw[0], bw[1], bw[2], bw[3]);
        sts128(bb + 16, bw[4], bw[5], bw[6], bw[7]);
    };

    lds(0); sts(0); lds(1);
    for (int it = 0; it < 32; ++it) {
        const int st = it & 1;
        __syncthreads();
        sts(it + 1);
        lds(it + 2);
#pragma unroll
        for (int ks = 0; ks < 2; ks++) {
            uint32_t a[2][4], b[2][4];
#pragma unroll
            for (int mi = 0; mi < 2; mi++) {
                uint32_t ro = (uint32_t)(st * 5120 +
                    (wm * 32 + mi * 16 + (lane & 15)) * WBROWB +
                    ks * 32 + (lane >> 4) * 16);
                ldsm4(a[mi], sAu + ro);
            }
#pragma unroll
            for (int p = 0; p < 2; p++) {
                uint32_t bo = (uint32_t)(st * 10240 +
                    (wn * 32 + p * 16 + (lane >> 4) * 8 + (lane & 7)) * WBROWB +
                    ks * 32 + ((lane >> 3) & 1) * 16);
                ldsm4(b[p], sBu + bo);
            }
#pragma unroll
            for (int mi = 0; mi < 2; mi++)
#pragma unroll
                for (int p = 0; p < 2; p++) {
                    mma_f16(acc[mi][2 * p],     a[mi], &b[p][0]);
                    mma_f16(acc[mi][2 * p + 1], a[mi], &b[p][2]);
                }
        }
    }

    float wg = g_wglobal[0];
#pragma unroll
    for (int mi = 0; mi < 2; mi++)
#pragma unroll
        for (int ni = 0; ni < 4; ni++) {
            int col = colBase + wn * 32 + ni * 8 + 2 * (lane & 3);
#pragma unroll
            for (int rh = 0; rh < 2; rh++) {
                int o = rowBase + wm * 32 + mi * 16 + (lane >> 2) + rh * 8;
                size_t base = (size_t)o * D_IN + col;
                float v0 = blend_one(w0[base], g0[base], acc[mi][ni][2 * rh], wg);
                float v1 = blend_one(w0[base + 1], g0[base + 1],
                                     acc[mi][ni][2 * rh + 1], wg);
                __half2 h2v = __floats2half2_rn(v0, v1);
                *(__half2*)(g_W0h + base) = h2v;
            }
        }
}

__global__ void w1_blend_kernel(const float* __restrict__ w1,
                                const float* __restrict__ g1,
                                const float* __restrict__ p1) {
    int i = blockIdx.x * blockDim.x + threadIdx.x;
    if (i >= D_H) return;
    float d = 0.f;
    for (int k = 0; k < D_H; k++) d += fabsf(w1[k] - g1[k]) * p1[i * D_H + k];
    g_W1b[i] = blend_one(w1[i], g1[i], d, g_wglobal[1]);
}

// ---------------- main GEMM (unchanged from R8) --------------------------
#define GBM 128
#define GBN 256
#define GBK 32
#define KITER (D_IN / GBK)   // 32
#define ROWB 80

#define A_OFF(st) ((uint32_t)((st) * 10240))
#define B_OFF(st) ((uint32_t)(20480 + (st) * 20480))
#define RED_OFF 81920u

__global__ __launch_bounds__(256, 1) void gemm_mma_kernel(
    const float* __restrict__ x, const float* __restrict__ b0, int Brows) {
    extern __shared__ char dsm[];
    const uint32_t sb = smem_u32(dsm);
    float* red = (float*)(dsm + RED_OFF);

    const int tid = threadIdx.x;
    const int wid = tid >> 5, lane = tid & 31;
    const int wm = wid >> 2;
    const int wn = wid & 3;
    const int colBlk = blockIdx.x;
    const int rowBase = blockIdx.y * GBM;
    const int nBase = colBlk * GBN;

    const int ar = tid >> 1, ah = tid & 1;
    const float* xrow = x + (size_t)(rowBase + ar) * D_IN + ah * 16;

    float acc[4][8][4] = {};
    float4 xr[4];

    auto load_B = [&](int it, int st) {
        if (it < KITER) {
            const __half* srcH = g_W0h + (size_t)nBase * D_IN + it * GBK;
#pragma unroll
            for (int i = 0; i < 4; i++) {
                int q = tid + i * 256;
                int r = q >> 2, g = q & 3;
                uint32_t doff = (uint32_t)(r * ROWB + g * 16);
                cp16(sb + B_OFF(st) + doff, srcH + (size_t)r * D_IN + g * 8);
            }
        }
        cp_commit();
    };

    auto lds_x = [&](int it) {
        if (it < KITER) {
#pragma unroll
            for (int j = 0; j < 4; j++)
                xr[j] = *(const float4*)(xrow + it * GBK + j * 4);
        }
    };

    auto sts_A = [&](int it) {
        if (it >= KITER) return;
        int st = it & 1;
        uint32_t hw[8];
#pragma unroll
        for (int j = 0; j < 4; j++) {
            float v4[4] = {xr[j].x, xr[j].y, xr[j].z, xr[j].w};
            unsigned short hh[4];
#pragma unroll
            for (int e = 0; e < 4; e++)
                hh[e] = __half_as_ushort(__float2half_rn(v4[e]));
            hw[2 * j]     = (uint32_t)hh[0] | ((uint32_t)hh[1] << 16);
            hw[2 * j + 1] = (uint32_t)hh[2] | ((uint32_t)hh[3] << 16);
        }
        uint32_t base = (uint32_t)(ar * ROWB + ah * 32);
        sts128(sb + A_OFF(st) + base,      hw[0], hw[1], hw[2], hw[3]);
        sts128(sb + A_OFF(st) + base + 16, hw[4], hw[5], hw[6], hw[7]);
    };

    lds_x(0);
    sts_A(0);
    lds_x(1);
    load_B(0, 0);
    load_B(1, 1);

    for (int it = 0; it < KITER; ++it) {
        const int ast = it & 1;
        const int bst = it % 3;
        cp_wait<1>();
        __syncthreads();
        sts_A(it + 1);
        lds_x(it + 2);
        load_B(it + 2, (it + 2) % 3);

        const uint32_t aS = sb + A_OFF(ast);
        const uint32_t bS = sb + B_OFF(bst);
#pragma unroll
        for (int ks = 0; ks < 2; ks++) {
            uint32_t a[4][4], b[4][4];
#pragma unroll
            for (int mi = 0; mi < 4; mi++) {
                uint32_t ro = (uint32_t)((wm * 64 + mi * 16 + (lane & 15)) * ROWB +
                                         ks * 32 + (lane >> 4) * 16);
                ldsm4(a[mi], aS + ro);
            }
#pragma unroll
            for (int p = 0; p < 4; p++) {
                uint32_t bo = (uint32_t)((wn * 64 + p * 16 + (lane >> 4) * 8 + (lane & 7)) * ROWB +
                                         ks * 32 + ((lane >> 3) & 1) * 16);
                ldsm4(b[p], bS + bo);
            }
#pragma unroll
            for (int mi = 0; mi < 4; mi++)
#pragma unroll
                for (int p = 0; p < 4; p++) {
                    mma_f16(acc[mi][2 * p],     a[mi], &b[p][0]);
                    mma_f16(acc[mi][2 * p + 1], a[mi], &b[p][2]);
                }
        }
    }

    float w1v[8][2], b0v[8][2];
#pragma unroll
    for (int ni = 0; ni < 8; ni++) {
        int c = nBase + wn * 64 + ni * 8 + 2 * (lane & 3);
        w1v[ni][0] = g_W1b[c];      w1v[ni][1] = g_W1b[c + 1];
        b0v[ni][0] = __ldg(b0 + c); b0v[ni][1] = __ldg(b0 + c + 1);
    }
#pragma unroll
    for (int mi = 0; mi < 4; mi++) {
        float r0 = 0.f, r1 = 0.f;
#pragma unroll
        for (int ni = 0; ni < 8; ni++) {
            r0 += fmaxf(acc[mi][ni][0] + b0v[ni][0], 0.f) * w1v[ni][0];
            r0 += fmaxf(acc[mi][ni][1] + b0v[ni][1], 0.f) * w1v[ni][1];
            r1 += fmaxf(acc[mi][ni][2] + b0v[ni][0], 0.f) * w1v[ni][0];
            r1 += fmaxf(acc[mi][ni][3] + b0v[ni][1], 0.f) * w1v[ni][1];
        }
        r0 += __shfl_xor_sync(0xffffffffu, r0, 1);
        r0 += __shfl_xor_sync(0xffffffffu, r0, 2);
        r1 += __shfl_xor_sync(0xffffffffu, r1, 1);
        r1 += __shfl_xor_sync(0xffffffffu, r1, 2);
        if ((lane & 3) == 0) {
            int rr = wm * 64 + mi * 16 + (lane >> 2);
            red[rr * 4 + wn] = r0;
            red[(rr + 8) * 4 + wn] = r1;
        }
    }
    __syncthreads();
    if (tid < GBM) {
        float s = red[tid * 4] + red[tid * 4 + 1] + red[tid * 4 + 2] + red[tid * 4 + 3];
        g_partial[(size_t)colBlk * Brows + rowBase + tid] = s;
    }
}

__global__ void reduce_kernel(float* __restrict__ out, const float* __restrict__ b1,
                              int Brows) {
    int b = blockIdx.x * blockDim.x + threadIdx.x;
    if (b < Brows)
        out[b] = b1[0] + g_partial[b] + g_partial[(size_t)Brows + b];
}

extern "C" void kernel_launch(void* const* d_in, const int* in_sizes, int n_in,
                              void* d_out, int out_size) {
    const float* x  = (const float*)d_in[0];
    const float* w0 = (const float*)d_in[1];
    const float* b0 = (const float*)d_in[2];
    const float* w1 = (const float*)d_in[3];
    const float* b1 = (const float*)d_in[4];
    const float* p0 = (const float*)d_in[5];
    const float* p1 = (const float*)d_in[6];
    const float* g0 = (const float*)d_in[7];
    const float* g1 = (const float*)d_in[8];
    float* out = (float*)d_out;
    int Brows = in_sizes[0] / D_IN;
    const int nbig4 = D_H * D_IN / 4;

    const int DYN = 83968;
    cudaFuncSetAttribute(gemm_mma_kernel,
                         cudaFuncAttributeMaxDynamicSharedMemorySize, DYN);

    init_kernel<<<1, 32>>>();
    minmax2_kernel<<<dim3(128, 2), 256>>>(w0, g0, nbig4);
    hist2_kernel<<<dim3(128, 2), 256>>>(w0, g0, nbig4);
    scalar_kernel<<<1, 256>>>(w1, g1);
    w0_blend_mma_kernel<<<dim3(D_IN / 128, D_H / 64), 256>>>(w0, g0, p0);
    w1_blend_kernel<<<2, 256>>>(w1, g1, p1);
    gemm_mma_kernel<<<dim3(2, Brows / GBM), 256, DYN>>>(x, b0, Brows);
    reduce_kernel<<<(Brows + 255) / 256, 256>>>(out, b1, Brows);
}